// round 7
// baseline (speedup 1.0000x reference)
#include <cuda_runtime.h>
#include <cuda_bf16.h>
#include <math.h>

#define BB 2
#define SS 2048
#define EE 768
#define HH 12
#define DK 64
#define WQ 384   // packed words per E-row

// ---------------- packed bf16 hi/lo storage (allocation-free) ----------------
__device__ unsigned g_Xh[3*4096*WQ],  g_Xl[3*4096*WQ];    // inputs q,k,v  [which][m][k2]
__device__ unsigned g_Wh[3*HH*WQ*64], g_Wl[3*HH*WQ*64];   // Wq/k/v [which][h][k2][n]
__device__ unsigned g_WOh[WQ*EE],     g_WOl[WQ*EE];       // W out  [k2][n]
__device__ unsigned g_Qh[BB*HH*SS*32], g_Ql[BB*HH*SS*32]; // Q [bhs][dk2]
__device__ unsigned g_Kh[BB*HH*SS*32], g_Kl[BB*HH*SS*32]; // K [bhs][dk2]
__device__ float    g_V [BB*HH*SS*DK];                    // V f32 [bhs][dk]
__device__ unsigned g_VTh[BB*HH*DK*1024], g_VTl[BB*HH*DK*1024]; // V^T [bhd][key2]
__device__ unsigned g_Ch[4096*WQ],    g_Cl[4096*WQ];      // concat [m][k2]

// Split two floats into packed bf16x2 hi and lo words (lo = residual).
__device__ __forceinline__ void split2(float x0, float x1, unsigned& hi, unsigned& lo) {
    __nv_bfloat162 h2 = __floats2bfloat162_rn(x0, x1);
    float h0 = __bfloat162float(__low2bfloat16(h2));
    float h1 = __bfloat162float(__high2bfloat16(h2));
    __nv_bfloat162 l2 = __floats2bfloat162_rn(x0 - h0, x1 - h1);
    hi = *reinterpret_cast<unsigned*>(&h2);
    lo = *reinterpret_cast<unsigned*>(&l2);
}

// D += A*B, m16n8k16 bf16, A row-major, B col-major, f32 accumulate.
__device__ __forceinline__ void mma16(float c[4], const unsigned a[4], const unsigned b[2]) {
    asm volatile(
        "mma.sync.aligned.m16n8k16.row.col.f32.bf16.bf16.f32 "
        "{%0,%1,%2,%3},{%4,%5,%6,%7},{%8,%9},{%0,%1,%2,%3};"
        : "+f"(c[0]), "+f"(c[1]), "+f"(c[2]), "+f"(c[3])
        : "r"(a[0]), "r"(a[1]), "r"(a[2]), "r"(a[3]), "r"(b[0]), "r"(b[1]));
}

// ---------------------------------------------------------------------------
// One-time conversions
// ---------------------------------------------------------------------------
__global__ __launch_bounds__(256) void conv_x(
    const float* __restrict__ q, const float* __restrict__ k, const float* __restrict__ v)
{
    int i = blockIdx.x * 256 + threadIdx.x;           // word index over 3 tensors
    const int N = 4096 * WQ;
    if (i >= 3*N) return;
    int which = i / N, j = i - which * N;
    const float* src = (which == 0) ? q : (which == 1) ? k : v;
    float2 x = ((const float2*)src)[j];
    split2(x.x, x.y, g_Xh[i], g_Xl[i]);
}

__global__ __launch_bounds__(256) void conv_w(
    const float* __restrict__ Wq, const float* __restrict__ Wk,
    const float* __restrict__ Wv, const float* __restrict__ Wo)
{
    int i = blockIdx.x * 256 + threadIdx.x;
    const int NW = 3 * HH * WQ * 64;                  // qkv weights
    if (i < NW) {
        int n = i & 63;
        int k2 = (i >> 6) % WQ;
        int h  = (i >> 6) / WQ % HH;
        int which = i / (HH * WQ * 64);
        const float* Ws = (which == 0) ? Wq : (which == 1) ? Wk : Wv;
        float x0 = Ws[((size_t)h*EE + 2*k2)     * DK + n];
        float x1 = Ws[((size_t)h*EE + 2*k2 + 1) * DK + n];
        split2(x0, x1, g_Wh[i], g_Wl[i]);
    } else {
        int j = i - NW;
        if (j >= WQ * EE) return;
        int n = j % EE, k2 = j / EE;
        float x0 = Wo[(size_t)(2*k2)     * EE + n];
        float x1 = Wo[(size_t)(2*k2 + 1) * EE + n];
        split2(x0, x1, g_WOh[j], g_WOl[j]);
    }
}

// Transpose V (f32 [bhs][dk]) -> packed-along-key hi/lo [bhd][key2].
__global__ __launch_bounds__(256) void vtrans_kernel()
{
    __shared__ float Vt[64][65];
    int kt = blockIdx.x, h = blockIdx.y, b = blockIdx.z;
    int t = threadIdx.x;
    size_t base = ((size_t)(b*HH + h)*SS + kt*64) * DK;
    #pragma unroll
    for (int i = 0; i < 16; i++) {
        int idx = t + i * 256;
        int key = idx >> 6, d = idx & 63;
        Vt[key][d] = g_V[base + key*DK + d];
    }
    __syncthreads();
    size_t obase = (size_t)(b*HH + h) * DK * 1024 + kt*32;
    #pragma unroll
    for (int i = 0; i < 8; i++) {
        int idx = t + i * 256;
        int d = idx >> 5, key2 = idx & 31;
        unsigned hi, lo;
        split2(Vt[2*key2][d], Vt[2*key2+1][d], hi, lo);
        g_VTh[obase + (size_t)d*1024 + key2] = hi;
        g_VTl[obase + (size_t)d*1024 + key2] = lo;
    }
}

// ---------------------------------------------------------------------------
// 3xBF16 GEMM, 64x64 tile, BK=32, 128 threads. Operands pre-packed in gmem.
// mode 0: QKV projections, grid=(M/64, H, 3); Q/K epilogue -> packed hi/lo,
//         V epilogue -> f32 g_V.
// mode 1: out projection, grid=(M/64, EE/64, 1), A = packed g_C, out -> f32.
// ---------------------------------------------------------------------------
#define GW 20

__global__ __launch_bounds__(128) void gemm_kernel(float* __restrict__ outp, int mode)
{
    __shared__ unsigned Ah[64*GW], Al[64*GW];   // [row][k2]
    __shared__ unsigned Bh[64*GW], Bl[64*GW];   // [n][k2]

    int bx = blockIdx.x, hn = blockIdx.y, which = blockIdx.z;
    int t = threadIdx.x, w = t >> 5, l = t & 31;
    int g = l >> 2, t4 = l & 3;
    int m0 = bx * 64;

    float acc[8][4] = {};
    int r0 = 16*w + g;

    for (int k0 = 0; k0 < WQ; k0 += 16) {       // k0 in words now
        __syncthreads();
        // A tile: 64 rows x 16 words
        #pragma unroll
        for (int i = 0; i < 8; i++) {
            int idx = t + i * 128;
            int r = idx >> 4, k2 = idx & 15;
            size_t src = (mode == 0)
                ? ((size_t)which*4096 + m0 + r) * WQ + k0 + k2
                : (size_t)(m0 + r) * WQ + k0 + k2;
            Ah[r*GW + k2] = (mode == 0) ? g_Xh[src] : g_Ch[src];
            Al[r*GW + k2] = (mode == 0) ? g_Xl[src] : g_Cl[src];
        }
        // B tile: 64 n x 16 words
        #pragma unroll
        for (int i = 0; i < 8; i++) {
            int idx = t + i * 128;
            int k2 = idx >> 6, n = idx & 63;
            if (mode == 0) {
                size_t src = (((size_t)which*HH + hn) * WQ + k0 + k2) * 64 + n;
                Bh[n*GW + k2] = g_Wh[src];
                Bl[n*GW + k2] = g_Wl[src];
            } else {
                size_t src = (size_t)(k0 + k2) * EE + hn*64 + n;
                Bh[n*GW + k2] = g_WOh[src];
                Bl[n*GW + k2] = g_WOl[src];
            }
        }
        __syncthreads();

        #pragma unroll
        for (int kc = 0; kc < 2; kc++) {
            int kw = kc*8 + t4;
            int ra = r0*GW + kw;
            unsigned ah[4] = {Ah[ra], Ah[ra + 8*GW], Ah[ra + 4], Ah[ra + 8*GW + 4]};
            unsigned al[4] = {Al[ra], Al[ra + 8*GW], Al[ra + 4], Al[ra + 8*GW + 4]};
            #pragma unroll
            for (int n0 = 0; n0 < 8; n0++) {
                int rb = (n0*8 + g)*GW + kw;
                unsigned bh2[2] = {Bh[rb], Bh[rb + 4]};
                unsigned bl2[2] = {Bl[rb], Bl[rb + 4]};
                mma16(acc[n0], ah, bh2);
                mma16(acc[n0], ah, bl2);
                mma16(acc[n0], al, bh2);
            }
        }
    }

    int rg1 = m0 + r0, rg2 = rg1 + 8;
    if (mode == 0) {
        int b1 = rg1 >> 11, s1 = rg1 & 2047;
        int b2 = rg2 >> 11, s2 = rg2 & 2047;
        if (which < 2) {
            unsigned* Gh = (which == 0) ? g_Qh : g_Kh;
            unsigned* Gl = (which == 0) ? g_Ql : g_Kl;
            size_t p1 = ((size_t)(b1*HH + hn)*SS + s1) * 32;
            size_t p2 = ((size_t)(b2*HH + hn)*SS + s2) * 32;
            #pragma unroll
            for (int n0 = 0; n0 < 8; n0++) {
                int wdx = n0*4 + t4;
                unsigned hi, lo;
                split2(acc[n0][0], acc[n0][1], hi, lo);
                Gh[p1 + wdx] = hi; Gl[p1 + wdx] = lo;
                split2(acc[n0][2], acc[n0][3], hi, lo);
                Gh[p2 + wdx] = hi; Gl[p2 + wdx] = lo;
            }
        } else {
            float* p1 = g_V + ((size_t)(b1*HH + hn)*SS + s1) * DK;
            float* p2 = g_V + ((size_t)(b2*HH + hn)*SS + s2) * DK;
            #pragma unroll
            for (int n0 = 0; n0 < 8; n0++) {
                int cn = n0*8 + 2*t4;
                *(float2*)&p1[cn] = make_float2(acc[n0][0], acc[n0][1]);
                *(float2*)&p2[cn] = make_float2(acc[n0][2], acc[n0][3]);
            }
        }
    } else {
        #pragma unroll
        for (int n0 = 0; n0 < 8; n0++) {
            int cn = hn*64 + n0*8 + 2*t4;
            *(float2*)&outp[(size_t)rg1 * EE + cn] = make_float2(acc[n0][0], acc[n0][1]);
            *(float2*)&outp[(size_t)rg2 * EE + cn] = make_float2(acc[n0][2], acc[n0][3]);
        }
    }
}

// ---------------------------------------------------------------------------
// Flash attention, 3xBF16. grid=(S/64, H, B), block=128 (4 warps).
// All operand tiles pre-packed in gmem -> smem staging is straight copies.
// Softmax scale (1/8) applied to scores post-mma (matches reference order).
// ---------------------------------------------------------------------------
#define KW 36
#define FLASH_SMEM (64*68*4 + 6*64*KW*4 + 3*64*4)

__global__ __launch_bounds__(128) void flash_kernel(const int* __restrict__ mask)
{
    extern __shared__ char smraw[];
    float*    Ss  = (float*)smraw;              // [64][68] fp32 scores
    unsigned* Kh  = (unsigned*)(Ss + 64*68);    // [64 key][KW]
    unsigned* Kl  = Kh  + 64*KW;
    unsigned* Vh  = Kl  + 64*KW;                // [64 dk][KW] (key-packed)
    unsigned* Vl  = Vh  + 64*KW;
    unsigned* P2h = Vl  + 64*KW;                // [64 q][KW] (Q staging, then P)
    unsigned* P2l = P2h + 64*KW;
    float* m_s    = (float*)(P2l + 64*KW);      // [64]
    float* l_s    = m_s + 64;
    float* corr_s = l_s + 64;

    int qt = blockIdx.x, h = blockIdx.y, b = blockIdx.z;
    int t = threadIdx.x, w = t >> 5, l = t & 31;
    int g = l >> 2, t4 = l & 3;
    int r0 = 16*w + g;

    size_t qbase = ((size_t)(b*HH + h)*SS + qt*64) * 32;
    size_t kbase = (size_t)(b*HH + h) * SS * 32;
    size_t vbase = (size_t)(b*HH + h) * DK * 1024;
    const int* Mp = mask + ((size_t)b*SS + qt*64) * SS;

    // Stage Q words, pull fragments to regs.
    #pragma unroll
    for (int i = 0; i < 16; i++) {
        int idx = t + i * 128;
        int r = idx >> 5, k2 = idx & 31;
        P2h[r*KW + k2] = g_Qh[qbase + r*32 + k2];
        P2l[r*KW + k2] = g_Ql[qbase + r*32 + k2];
    }
    if (t < 64) { m_s[t] = -INFINITY; l_s[t] = 0.f; }
    __syncthreads();

    unsigned qfh[4][4], qfl[4][4];
    #pragma unroll
    for (int kc = 0; kc < 4; kc++) {
        int ra = r0*KW + kc*8 + t4;
        qfh[kc][0] = P2h[ra];     qfh[kc][1] = P2h[ra + 8*KW];
        qfh[kc][2] = P2h[ra + 4]; qfh[kc][3] = P2h[ra + 8*KW + 4];
        qfl[kc][0] = P2l[ra];     qfl[kc][1] = P2l[ra + 8*KW];
        qfl[kc][2] = P2l[ra + 4]; qfl[kc][3] = P2l[ra + 8*KW + 4];
    }

    float acc[8][4] = {};

    for (int kt = 0; kt < SS/64; kt++) {
        __syncthreads();
        // K tile: straight copy [key][dk2]
        #pragma unroll
        for (int i = 0; i < 16; i++) {
            int idx = t + i * 128;
            int r = idx >> 5, k2 = idx & 31;
            Kh[r*KW + k2] = g_Kh[kbase + (kt*64 + r)*32 + k2];
            Kl[r*KW + k2] = g_Kl[kbase + (kt*64 + r)*32 + k2];
        }
        // V^T tile: straight copy [dk][key2]
        #pragma unroll
        for (int i = 0; i < 16; i++) {
            int idx = t + i * 128;
            int d = idx >> 5, key2 = idx & 31;
            Vh[d*KW + key2] = g_VTh[vbase + (size_t)d*1024 + kt*32 + key2];
            Vl[d*KW + key2] = g_VTl[vbase + (size_t)d*1024 + kt*32 + key2];
        }
        __syncthreads();

        // ---- QK^T (3x bf16) ----
        float sacc[8][4] = {};
        #pragma unroll
        for (int kc = 0; kc < 4; kc++) {
            #pragma unroll
            for (int n0 = 0; n0 < 8; n0++) {
                int rb = (n0*8 + g)*KW + kc*8 + t4;
                unsigned bh2[2] = {Kh[rb], Kh[rb + 4]};
                unsigned bl2[2] = {Kl[rb], Kl[rb + 4]};
                mma16(sacc[n0], qfh[kc], bh2);
                mma16(sacc[n0], qfh[kc], bl2);
                mma16(sacc[n0], qfl[kc], bh2);
            }
        }
        #pragma unroll
        for (int n0 = 0; n0 < 8; n0++) {
            int cc = n0*8 + 2*t4;
            *(float2*)&Ss[r0*68 + cc]     = make_float2(sacc[n0][0], sacc[n0][1]);
            *(float2*)&Ss[(r0+8)*68 + cc] = make_float2(sacc[n0][2], sacc[n0][3]);
        }
        __syncwarp();

        // ---- masked online softmax (lane pair per row: 32 cols each) ----
        {
            int row = 16*w + (l >> 1);
            int j0 = (l & 1) * 32;
            const int* Mr = Mp + (size_t)row * SS + kt*64 + j0;
            float s[32];
            #pragma unroll
            for (int i = 0; i < 8; i++) {
                float4 v = *(const float4*)&Ss[row*68 + j0 + i*4];
                s[i*4] = v.x; s[i*4+1] = v.y; s[i*4+2] = v.z; s[i*4+3] = v.w;
            }
            #pragma unroll
            for (int i = 0; i < 8; i++) {
                int4 mm = *(const int4*)&Mr[i*4];
                s[i*4]   = mm.x ? s[i*4]   * 0.125f : -1e9f;
                s[i*4+1] = mm.y ? s[i*4+1] * 0.125f : -1e9f;
                s[i*4+2] = mm.z ? s[i*4+2] * 0.125f : -1e9f;
                s[i*4+3] = mm.w ? s[i*4+3] * 0.125f : -1e9f;
            }
            float mx = -INFINITY;
            #pragma unroll
            for (int j = 0; j < 32; j++) mx = fmaxf(mx, s[j]);
            mx = fmaxf(mx, __shfl_xor_sync(0xffffffffu, mx, 1));
            float mold = m_s[row];
            float mnew = fmaxf(mold, mx);
            float corr = __expf(mold - mnew);
            float ls = 0.f;
            #pragma unroll
            for (int j = 0; j < 32; j++) {
                float p = __expf(s[j] - mnew);
                s[j] = p;
                ls += p;
            }
            ls += __shfl_xor_sync(0xffffffffu, ls, 1);
            int c0 = (l & 1) * 16;
            #pragma unroll
            for (int i = 0; i < 16; i++)
                split2(s[2*i], s[2*i+1], P2h[row*KW + c0 + i], P2l[row*KW + c0 + i]);
            m_s[row] = mnew;
            l_s[row] = l_s[row] * corr + ls;
            corr_s[row] = corr;
        }
        __syncwarp();

        // ---- PV (3x bf16) ----
        float cr1 = corr_s[r0];
        float cr2 = corr_s[r0 + 8];
        #pragma unroll
        for (int n0 = 0; n0 < 8; n0++) {
            acc[n0][0] *= cr1; acc[n0][1] *= cr1;
            acc[n0][2] *= cr2; acc[n0][3] *= cr2;
        }
        #pragma unroll
        for (int kc = 0; kc < 4; kc++) {
            int ra = r0*KW + kc*8 + t4;
            unsigned ah[4] = {P2h[ra], P2h[ra + 8*KW], P2h[ra + 4], P2h[ra + 8*KW + 4]};
            unsigned al[4] = {P2l[ra], P2l[ra + 8*KW], P2l[ra + 4], P2l[ra + 8*KW + 4]};
            #pragma unroll
            for (int n0 = 0; n0 < 8; n0++) {
                int rb = (n0*8 + g)*KW + kc*8 + t4;
                unsigned bh2[2] = {Vh[rb], Vh[rb + 4]};
                unsigned bl2[2] = {Vl[rb], Vl[rb + 4]};
                mma16(acc[n0], ah, bh2);
                mma16(acc[n0], ah, bl2);
                mma16(acc[n0], al, bh2);
            }
        }
    }

    __syncwarp();
    float inv1 = 1.f / l_s[r0];
    float inv2 = 1.f / l_s[r0 + 8];
    size_t row1 = (size_t)b*SS + qt*64 + r0;
    #pragma unroll
    for (int n0 = 0; n0 < 8; n0++) {
        int wdx = h*32 + n0*4 + t4;
        unsigned hi, lo;
        split2(acc[n0][0]*inv1, acc[n0][1]*inv1, hi, lo);
        g_Ch[row1*WQ + wdx] = hi; g_Cl[row1*WQ + wdx] = lo;
        split2(acc[n0][2]*inv2, acc[n0][3]*inv2, hi, lo);
        g_Ch[(row1+8)*WQ + wdx] = hi; g_Cl[(row1+8)*WQ + wdx] = lo;
    }
}

// ---------------------------------------------------------------------------
extern "C" void kernel_launch(void* const* d_in, const int* in_sizes, int n_in,
                              void* d_out, int out_size)
{
    const float* q    = (const float*)d_in[0];
    const float* k    = (const float*)d_in[1];
    const float* v    = (const float*)d_in[2];
    const int*   mask = (const int*)  d_in[3];
    const float* Wq   = (const float*)d_in[4];
    const float* Wk   = (const float*)d_in[5];
    const float* Wv   = (const float*)d_in[6];
    const float* W    = (const float*)d_in[7];
    float* out = (float*)d_out;

    cudaFuncSetAttribute(flash_kernel,
                         cudaFuncAttributeMaxDynamicSharedMemorySize, FLASH_SMEM);

    // one-time packs
    conv_x<<<(3*4096*WQ + 255)/256, 256>>>(q, k, v);
    conv_w<<<(3*HH*WQ*64 + WQ*EE + 255)/256, 256>>>(Wq, Wk, Wv, W);

    // QKV projections
    gemm_kernel<<<dim3((BB*SS)/64, HH, 3), 128>>>(nullptr, 0);

    // V transpose+pack
    vtrans_kernel<<<dim3(SS/64, HH, BB), 256>>>();

    // Flash attention
    flash_kernel<<<dim3(SS/64, HH, BB), 128, FLASH_SMEM>>>(mask);

    // Output projection
    gemm_kernel<<<dim3((BB*SS)/64, EE/64, 1), 128>>>(out, 1);
}

// round 8
// speedup vs baseline: 1.1754x; 1.1754x over previous
#include <cuda_runtime.h>
#include <cuda_bf16.h>
#include <math.h>

#define BB 2
#define SS 2048
#define EE 768
#define HH 12
#define DK 64

// Scratch (allocation-free: __device__ globals)
__device__ float g_Q[BB*HH*SS*DK];   // [B,H,S,Dk]
__device__ float g_K[BB*HH*SS*DK];
__device__ float g_V[BB*HH*SS*DK];
__device__ float g_C[BB*SS*EE];      // concat [B,S,H*Dk]

// Split two floats into packed bf16x2 hi and lo words (lo = residual).
__device__ __forceinline__ void split2(float x0, float x1, unsigned& hi, unsigned& lo) {
    __nv_bfloat162 h2 = __floats2bfloat162_rn(x0, x1);
    float h0 = __bfloat162float(__low2bfloat16(h2));
    float h1 = __bfloat162float(__high2bfloat16(h2));
    __nv_bfloat162 l2 = __floats2bfloat162_rn(x0 - h0, x1 - h1);
    hi = *reinterpret_cast<unsigned*>(&h2);
    lo = *reinterpret_cast<unsigned*>(&l2);
}

// D += A*B, m16n8k16 bf16, A row-major, B col-major, f32 accumulate.
__device__ __forceinline__ void mma16(float c[4], const unsigned a[4], const unsigned* b) {
    asm volatile(
        "mma.sync.aligned.m16n8k16.row.col.f32.bf16.bf16.f32 "
        "{%0,%1,%2,%3},{%4,%5,%6,%7},{%8,%9},{%0,%1,%2,%3};"
        : "+f"(c[0]), "+f"(c[1]), "+f"(c[2]), "+f"(c[3])
        : "r"(a[0]), "r"(a[1]), "r"(a[2]), "r"(a[3]), "r"(b[0]), "r"(b[1]));
}

// ldmatrix x4: 4 8x8 b16 matrices; each lane supplies one row address.
__device__ __forceinline__ void ldsm_x4(unsigned r[4], const void* p) {
    unsigned addr = (unsigned)__cvta_generic_to_shared(p);
    asm volatile("ldmatrix.sync.aligned.m8n8.x4.shared.b16 {%0,%1,%2,%3}, [%4];"
                 : "=r"(r[0]), "=r"(r[1]), "=r"(r[2]), "=r"(r[3]) : "r"(addr));
}

// ---------------------------------------------------------------------------
// 3xBF16 GEMM, 64x64 block tile, BK=32, 128 threads (4 warps x 16 rows).
// Tiles stored as packed bf16x2 words along K, word stride 20 (8-row LDSM
// phases touch all 32 banks exactly once -> conflict-free).
// mode 0: QKV projections. grid=(M/64, H, 3).
// mode 1: out projection. grid=(M/64, EE/64, 1).
// ---------------------------------------------------------------------------
#define GW 20

__global__ __launch_bounds__(128) void gemm_kernel(
    const float* __restrict__ Xq, const float* __restrict__ Xk, const float* __restrict__ Xv,
    const float* __restrict__ Wq, const float* __restrict__ Wk, const float* __restrict__ Wv,
    const float* __restrict__ Wo, float* __restrict__ outp, int mode)
{
    __shared__ unsigned Ah[64*GW], Al[64*GW];   // [row][k2]
    __shared__ unsigned Bh[64*GW], Bl[64*GW];   // [n][k2]

    int bx = blockIdx.x, hn = blockIdx.y, which = blockIdx.z;
    int t = threadIdx.x, w = t >> 5, l = t & 31;
    int g = l >> 2, t4 = l & 3;
    int lj = l >> 3;                 // ldmatrix quadrant
    int lr = l & 7;                  // ldmatrix row-within-quadrant
    int m0 = bx * 64;

    const float* A;
    const float* Bw;
    int ldb;
    if (mode == 0) {
        A = (which == 0) ? Xq : (which == 1) ? Xk : Xv;
        const float* Ws = (which == 0) ? Wq : (which == 1) ? Wk : Wv;
        Bw = Ws + (size_t)hn * EE * DK;
        ldb = DK;
    } else {
        A = g_C;
        Bw = Wo + hn * 64;
        ldb = EE;
    }

    float acc[8][4] = {};
    int r0 = 16*w + g;   // fragment row base

    // ldmatrix lane address components
    int arow = 16*w + lr + (lj & 1) * 8;     // A: quadrants 0/1 rows, 2/3 k-half
    int acol_q = (lj >> 1) * 4;
    int brow_off = lr + (lj >> 1) * 8;       // B: quadrants 0/1 k-half, 2/3 rows+8
    int bcol_q = (lj & 1) * 4;

    for (int k0 = 0; k0 < EE; k0 += 32) {
        __syncthreads();
        // A tile: 64 rows x 16 k-words
        #pragma unroll
        for (int i = 0; i < 8; i++) {
            int idx = t + i * 128;
            int r = idx >> 4, k2 = idx & 15;
            float2 x = *(const float2*)&A[(size_t)(m0 + r) * EE + k0 + 2*k2];
            split2(x.x, x.y, Ah[r*GW + k2], Al[r*GW + k2]);
        }
        // B tile: [n][k2] (transposed pack from K-major gmem)
        #pragma unroll
        for (int i = 0; i < 8; i++) {
            int idx = t + i * 128;
            int n = idx & 63, k2 = idx >> 6;
            float x0 = Bw[(size_t)(k0 + 2*k2)     * ldb + n];
            float x1 = Bw[(size_t)(k0 + 2*k2 + 1) * ldb + n];
            split2(x0, x1, Bh[n*GW + k2], Bl[n*GW + k2]);
        }
        __syncthreads();

        #pragma unroll
        for (int kc = 0; kc < 2; kc++) {
            unsigned ah[4], al[4];
            ldsm_x4(ah, &Ah[arow*GW + kc*8 + acol_q]);
            ldsm_x4(al, &Al[arow*GW + kc*8 + acol_q]);
            #pragma unroll
            for (int n0p = 0; n0p < 4; n0p++) {
                unsigned bh[4], bl[4];
                int br = (n0p*16 + brow_off)*GW + kc*8 + bcol_q;
                ldsm_x4(bh, &Bh[br]);
                ldsm_x4(bl, &Bl[br]);
                mma16(acc[2*n0p],   ah, bh);
                mma16(acc[2*n0p],   ah, bl);
                mma16(acc[2*n0p],   al, bh);
                mma16(acc[2*n0p+1], ah, bh+2);
                mma16(acc[2*n0p+1], ah, bl+2);
                mma16(acc[2*n0p+1], al, bh+2);
            }
        }
    }

    // Epilogue: lane covers rows r0, r0+8; cols n0*8 + 2*t4, +1.
    int rg1 = m0 + r0, rg2 = rg1 + 8;
    if (mode == 0) {
        float* G = (which == 0) ? g_Q : (which == 1) ? g_K : g_V;
        int b1 = rg1 >> 11, s1 = rg1 & 2047;
        int b2 = rg2 >> 11, s2 = rg2 & 2047;
        float* p1 = G + ((size_t)(b1*HH + hn)*SS + s1) * DK;
        float* p2 = G + ((size_t)(b2*HH + hn)*SS + s2) * DK;
        #pragma unroll
        for (int n0 = 0; n0 < 8; n0++) {
            int cn = n0*8 + 2*t4;
            *(float2*)&p1[cn] = make_float2(acc[n0][0], acc[n0][1]);
            *(float2*)&p2[cn] = make_float2(acc[n0][2], acc[n0][3]);
        }
    } else {
        #pragma unroll
        for (int n0 = 0; n0 < 8; n0++) {
            int cn = hn*64 + n0*8 + 2*t4;
            *(float2*)&outp[(size_t)rg1 * EE + cn] = make_float2(acc[n0][0], acc[n0][1]);
            *(float2*)&outp[(size_t)rg2 * EE + cn] = make_float2(acc[n0][2], acc[n0][3]);
        }
    }
}

// ---------------------------------------------------------------------------
// Flash attention, 3xBF16 tensor cores + ldmatrix. grid=(S/64, H, B),
// block=128 (4 warps). Warp w owns query rows [16w, 16w+16). Q hi/lo
// fragments in registers (pre-scaled by 1/8). Packed word stride 36.
// ---------------------------------------------------------------------------
#define KW 36
#define FLASH_SMEM (64*68*4 + 6*64*KW*4 + 3*64*4)

__global__ __launch_bounds__(128) void flash_kernel(const int* __restrict__ mask)
{
    extern __shared__ char smraw[];
    float*    Ss  = (float*)smraw;              // [64][68] fp32 scores
    unsigned* Kh  = (unsigned*)(Ss + 64*68);    // [64 key][KW]
    unsigned* Kl  = Kh  + 64*KW;
    unsigned* Vh  = Kl  + 64*KW;                // [64 dk][KW] (key-packed)
    unsigned* Vl  = Vh  + 64*KW;
    unsigned* P2h = Vl  + 64*KW;                // [64 q][KW] (Q staging, then P)
    unsigned* P2l = P2h + 64*KW;
    float* m_s    = (float*)(P2l + 64*KW);      // [64]
    float* l_s    = m_s + 64;
    float* corr_s = l_s + 64;

    int qt = blockIdx.x, h = blockIdx.y, b = blockIdx.z;
    int t = threadIdx.x, w = t >> 5, l = t & 31;
    int g = l >> 2, t4 = l & 3;
    int lj = l >> 3, lr = l & 7;
    int r0 = 16*w + g;

    const float* Qp = g_Q + ((size_t)(b*HH + h)*SS + qt*64) * DK;
    const float* Kp = g_K + (size_t)(b*HH + h) * SS * DK;
    const float* Vp = g_V + (size_t)(b*HH + h) * SS * DK;
    const int*   Mp = mask + ((size_t)b*SS + qt*64) * SS;

    int arow = 16*w + lr + (lj & 1) * 8;
    int acol_q = (lj >> 1) * 4;
    int brow_off = lr + (lj >> 1) * 8;
    int bcol_q = (lj & 1) * 4;

    // Stage Q (x 1/8) hi/lo packed into P2h/P2l, then pull fragments to regs.
    #pragma unroll
    for (int i = 0; i < 16; i++) {
        int idx = t + i * 128;
        int r = idx >> 5, k2 = idx & 31;
        float2 x = *(const float2*)&Qp[r*DK + 2*k2];
        split2(x.x * 0.125f, x.y * 0.125f, P2h[r*KW + k2], P2l[r*KW + k2]);
    }
    if (t < 64) { m_s[t] = -INFINITY; l_s[t] = 0.f; }
    __syncthreads();

    unsigned qfh[4][4], qfl[4][4];
    #pragma unroll
    for (int kc = 0; kc < 4; kc++) {
        ldsm_x4(qfh[kc], &P2h[arow*KW + kc*8 + acol_q]);
        ldsm_x4(qfl[kc], &P2l[arow*KW + kc*8 + acol_q]);
    }

    float acc[8][4] = {};

    for (int kt = 0; kt < SS/64; kt++) {
        __syncthreads();
        const float* Kt = Kp + (size_t)kt * 64 * DK;
        const float* Vt = Vp + (size_t)kt * 64 * DK;
        // K tile: [key][dk2], straight pack
        #pragma unroll
        for (int i = 0; i < 16; i++) {
            int idx = t + i * 128;
            int r = idx >> 5, k2 = idx & 31;
            float2 x = *(const float2*)&Kt[r*DK + 2*k2];
            split2(x.x, x.y, Kh[r*KW + k2], Kl[r*KW + k2]);
        }
        // V tile transposed: [dk][key2], pack across key pairs
        #pragma unroll
        for (int i = 0; i < 16; i++) {
            int idx = t + i * 128;
            int d = idx & 63, key2 = idx >> 6;
            float x0 = Vt[(2*key2)     * DK + d];
            float x1 = Vt[(2*key2 + 1) * DK + d];
            split2(x0, x1, Vh[d*KW + key2], Vl[d*KW + key2]);
        }
        __syncthreads();

        // ---- QK^T (3x bf16, ldmatrix B) ----
        float sacc[8][4] = {};
        #pragma unroll
        for (int kc = 0; kc < 4; kc++) {
            #pragma unroll
            for (int n0p = 0; n0p < 4; n0p++) {
                unsigned bh[4], bl[4];
                int br = (n0p*16 + brow_off)*KW + kc*8 + bcol_q;
                ldsm_x4(bh, &Kh[br]);
                ldsm_x4(bl, &Kl[br]);
                mma16(sacc[2*n0p],   qfh[kc], bh);
                mma16(sacc[2*n0p],   qfh[kc], bl);
                mma16(sacc[2*n0p],   qfl[kc], bh);
                mma16(sacc[2*n0p+1], qfh[kc], bh+2);
                mma16(sacc[2*n0p+1], qfh[kc], bl+2);
                mme_dummy: ;
                mma16(sacc[2*n0p+1], qfl[kc], bh+2);
            }
        }
        #pragma unroll
        for (int n0 = 0; n0 < 8; n0++) {
            int cc = n0*8 + 2*t4;
            *(float2*)&Ss[r0*68 + cc]     = make_float2(sacc[n0][0], sacc[n0][1]);
            *(float2*)&Ss[(r0+8)*68 + cc] = make_float2(sacc[n0][2], sacc[n0][3]);
        }
        __syncwarp();

        // ---- masked online softmax (lane pair per row: 32 cols each) ----
        {
            int row = 16*w + (l >> 1);
            int j0 = (l & 1) * 32;
            const int* Mr = Mp + (size_t)row * SS + kt*64 + j0;
            float s[32];
            #pragma unroll
            for (int i = 0; i < 8; i++) {
                float4 v = *(const float4*)&Ss[row*68 + j0 + i*4];
                s[i*4] = v.x; s[i*4+1] = v.y; s[i*4+2] = v.z; s[i*4+3] = v.w;
            }
            #pragma unroll
            for (int i = 0; i < 8; i++) {
                int4 mm = *(const int4*)&Mr[i*4];
                s[i*4]   = mm.x ? s[i*4]   : -1e9f;
                s[i*4+1] = mm.y ? s[i*4+1] : -1e9f;
                s[i*4+2] = mm.z ? s[i*4+2] : -1e9f;
                s[i*4+3] = mm.w ? s[i*4+3] : -1e9f;
            }
            float mx = -INFINITY;
            #pragma unroll
            for (int j = 0; j < 32; j++) mx = fmaxf(mx, s[j]);
            mx = fmaxf(mx, __shfl_xor_sync(0xffffffffu, mx, 1));
            float mold = m_s[row];
            float mnew = fmaxf(mold, mx);
            float corr = __expf(mold - mnew);   // 0 on first tile (mold=-inf)
            float ls = 0.f;
            #pragma unroll
            for (int j = 0; j < 32; j++) {
                float p = __expf(s[j] - mnew);
                s[j] = p;
                ls += p;
            }
            ls += __shfl_xor_sync(0xffffffffu, ls, 1);
            int c0 = (l & 1) * 16;
            #pragma unroll
            for (int i = 0; i < 16; i++)
                split2(s[2*i], s[2*i+1], P2h[row*KW + c0 + i], P2l[row*KW + c0 + i]);
            m_s[row] = mnew;
            l_s[row] = l_s[row] * corr + ls;
            corr_s[row] = corr;
        }
        __syncwarp();

        // ---- PV (3x bf16, ldmatrix A and B) ----
        float cr1 = corr_s[r0];
        float cr2 = corr_s[r0 + 8];
        #pragma unroll
        for (int n0 = 0; n0 < 8; n0++) {
            acc[n0][0] *= cr1; acc[n0][1] *= cr1;
            acc[n0][2] *= cr2; acc[n0][3] *= cr2;
        }
        #pragma unroll
        for (int kc = 0; kc < 4; kc++) {
            unsigned ah[4], al[4];
            ldsm_x4(ah, &P2h[arow*KW + kc*8 + acol_q]);
            ldsm_x4(al, &P2l[arow*KW + kc*8 + acol_q]);
            #pragma unroll
            for (int n0p = 0; n0p < 4; n0p++) {
                unsigned bh[4], bl[4];
                int br = (n0p*16 + brow_off)*KW + kc*8 + bcol_q;
                ldsm_x4(bh, &Vh[br]);
                ldsm_x4(bl, &Vl[br]);
                mma16(acc[2*n0p],   ah, bh);
                mma16(acc[2*n0p],   ah, bl);
                mma16(acc[2*n0p],   al, bh);
                mma16(acc[2*n0p+1], ah, bh+2);
                mma16(acc[2*n0p+1], ah, bl+2);
                mma16(acc[2*n0p+1], al, bh+2);
            }
        }
    }

    __syncwarp();
    float inv1 = 1.f / l_s[r0];
    float inv2 = 1.f / l_s[r0 + 8];
    int row1 = qt*64 + r0;
    float* Cb = g_C + (size_t)b * SS * EE + (size_t)h * DK;
    #pragma unroll
    for (int n0 = 0; n0 < 8; n0++) {
        int cc = n0*8 + 2*t4;
        *(float2*)&Cb[(size_t)row1 * EE + cc] =
            make_float2(acc[n0][0]*inv1, acc[n0][1]*inv1);
        *(float2*)&Cb[(size_t)(row1+8) * EE + cc] =
            make_float2(acc[n0][2]*inv2, acc[n0][3]*inv2);
    }
}

// ---------------------------------------------------------------------------
extern "C" void kernel_launch(void* const* d_in, const int* in_sizes, int n_in,
                              void* d_out, int out_size)
{
    const float* q    = (const float*)d_in[0];
    const float* k    = (const float*)d_in[1];
    const float* v    = (const float*)d_in[2];
    const int*   mask = (const int*)  d_in[3];
    const float* Wq   = (const float*)d_in[4];
    const float* Wk   = (const float*)d_in[5];
    const float* Wv   = (const float*)d_in[6];
    const float* W    = (const float*)d_in[7];
    float* out = (float*)d_out;

    cudaFuncSetAttribute(flash_kernel,
                         cudaFuncAttributeMaxDynamicSharedMemorySize, FLASH_SMEM);

    // QKV projections (3xBF16 tensor cores)
    gemm_kernel<<<dim3((BB*SS)/64, HH, 3), 128>>>(q, k, v, Wq, Wk, Wv, nullptr, nullptr, 0);

    // Flash attention (3xBF16 tensor cores)
    flash_kernel<<<dim3(SS/64, HH, BB), 128, FLASH_SMEM>>>(mask);

    // Output projection (3xBF16 tensor cores)
    gemm_kernel<<<dim3((BB*SS)/64, EE/64, 1), 128>>>(nullptr, nullptr, nullptr,
                                                     nullptr, nullptr, nullptr, W, out, 1);
}

// round 10
// speedup vs baseline: 1.1850x; 1.0081x over previous
#include <cuda_runtime.h>
#include <cuda_bf16.h>
#include <math.h>

#define BB 2
#define SS 2048
#define EE 768
#define HH 12
#define DK 64

// Scratch (allocation-free: __device__ globals)
__device__ float g_Q[BB*HH*SS*DK];   // [B,H,S,Dk]
__device__ float g_K[BB*HH*SS*DK];
__device__ float g_V[BB*HH*SS*DK];
__device__ float g_C[BB*SS*EE];      // concat [B,S,H*Dk]

// Split two floats into packed bf16x2 hi and lo words (lo = residual).
__device__ __forceinline__ void split2(float x0, float x1, unsigned& hi, unsigned& lo) {
    __nv_bfloat162 h2 = __floats2bfloat162_rn(x0, x1);
    float h0 = __bfloat162float(__low2bfloat16(h2));
    float h1 = __bfloat162float(__high2bfloat16(h2));
    __nv_bfloat162 l2 = __floats2bfloat162_rn(x0 - h0, x1 - h1);
    hi = *reinterpret_cast<unsigned*>(&h2);
    lo = *reinterpret_cast<unsigned*>(&l2);
}

// D += A*B, m16n8k16 bf16, A row-major, B col-major, f32 accumulate.
__device__ __forceinline__ void mma16(float c[4], const unsigned a[4], const unsigned* b) {
    asm volatile(
        "mma.sync.aligned.m16n8k16.row.col.f32.bf16.bf16.f32 "
        "{%0,%1,%2,%3},{%4,%5,%6,%7},{%8,%9},{%0,%1,%2,%3};"
        : "+f"(c[0]), "+f"(c[1]), "+f"(c[2]), "+f"(c[3])
        : "r"(a[0]), "r"(a[1]), "r"(a[2]), "r"(a[3]), "r"(b[0]), "r"(b[1]));
}

// ldmatrix x4: 4 8x8 b16 matrices; each lane supplies one row address.
__device__ __forceinline__ void ldsm_x4(unsigned r[4], const void* p) {
    unsigned addr = (unsigned)__cvta_generic_to_shared(p);
    asm volatile("ldmatrix.sync.aligned.m8n8.x4.shared.b16 {%0,%1,%2,%3}, [%4];"
                 : "=r"(r[0]), "=r"(r[1]), "=r"(r[2]), "=r"(r[3]) : "r"(addr));
}

// ---------------------------------------------------------------------------
// 3xBF16 GEMM, 64x64 tile, BK=32, 128 threads, register-prefetch pipelined.
// mode 0: QKV projections. grid=(M/64, H, 3).
// mode 1: out projection. grid=(M/64, EE/64, 1).
// ---------------------------------------------------------------------------
#define GW 20

__global__ __launch_bounds__(128) void gemm_kernel(
    const float* __restrict__ Xq, const float* __restrict__ Xk, const float* __restrict__ Xv,
    const float* __restrict__ Wq, const float* __restrict__ Wk, const float* __restrict__ Wv,
    const float* __restrict__ Wo, float* __restrict__ outp, int mode)
{
    __shared__ unsigned Ah[64*GW], Al[64*GW];   // [row][k2]
    __shared__ unsigned Bh[64*GW], Bl[64*GW];   // [n][k2]

    int bx = blockIdx.x, hn = blockIdx.y, which = blockIdx.z;
    int t = threadIdx.x, w = t >> 5, l = t & 31;
    int t4 = l & 3;
    int g = l >> 2;
    int lj = l >> 3, lr = l & 7;
    int m0 = bx * 64;

    const float* A;
    const float* Bw;
    int ldb;
    if (mode == 0) {
        A = (which == 0) ? Xq : (which == 1) ? Xk : Xv;
        const float* Ws = (which == 0) ? Wq : (which == 1) ? Wk : Wv;
        Bw = Ws + (size_t)hn * EE * DK;
        ldb = DK;
    } else {
        A = g_C;
        Bw = Wo + hn * 64;
        ldb = EE;
    }

    float acc[8][4] = {};
    int r0 = 16*w + g;

    int arow = 16*w + lr + (lj & 1) * 8;
    int acol_q = (lj >> 1) * 4;
    int brow_off = lr + (lj >> 1) * 8;
    int bcol_q = (lj & 1) * 4;

    // addressing for staging
    int ar = t >> 4, ak2 = t & 15;          // with i*8 row step
    int bn = t & 63, bk2 = t >> 6;          // with i*2 k2 step

    float2 pa[8];
    float  pb0[8], pb1[8];

    // prefetch k0 = 0
    #pragma unroll
    for (int i = 0; i < 8; i++)
        pa[i] = *(const float2*)&A[(size_t)(m0 + ar + i*8) * EE + 2*ak2];
    #pragma unroll
    for (int i = 0; i < 8; i++) {
        pb0[i] = Bw[(size_t)(2*(bk2 + i*2))     * ldb + bn];
        pb1[i] = Bw[(size_t)(2*(bk2 + i*2) + 1) * ldb + bn];
    }

    for (int k0 = 0; k0 < EE; k0 += 32) {
        __syncthreads();
        #pragma unroll
        for (int i = 0; i < 8; i++)
            split2(pa[i].x, pa[i].y, Ah[(ar + i*8)*GW + ak2], Al[(ar + i*8)*GW + ak2]);
        #pragma unroll
        for (int i = 0; i < 8; i++)
            split2(pb0[i], pb1[i], Bh[bn*GW + bk2 + i*2], Bl[bn*GW + bk2 + i*2]);
        __syncthreads();

        if (k0 + 32 < EE) {
            int kn = k0 + 32;
            #pragma unroll
            for (int i = 0; i < 8; i++)
                pa[i] = *(const float2*)&A[(size_t)(m0 + ar + i*8) * EE + kn + 2*ak2];
            #pragma unroll
            for (int i = 0; i < 8; i++) {
                pb0[i] = Bw[(size_t)(kn + 2*(bk2 + i*2))     * ldb + bn];
                pb1[i] = Bw[(size_t)(kn + 2*(bk2 + i*2) + 1) * ldb + bn];
            }
        }

        #pragma unroll
        for (int kc = 0; kc < 2; kc++) {
            unsigned ah[4], al[4];
            ldsm_x4(ah, &Ah[arow*GW + kc*8 + acol_q]);
            ldsm_x4(al, &Al[arow*GW + kc*8 + acol_q]);
            #pragma unroll
            for (int n0p = 0; n0p < 4; n0p++) {
                unsigned bh[4], bl[4];
                int br = (n0p*16 + brow_off)*GW + kc*8 + bcol_q;
                ldsm_x4(bh, &Bh[br]);
                ldsm_x4(bl, &Bl[br]);
                mma16(acc[2*n0p],   ah, bh);
                mma16(acc[2*n0p],   ah, bl);
                mma16(acc[2*n0p],   al, bh);
                mma16(acc[2*n0p+1], ah, bh+2);
                mma16(acc[2*n0p+1], ah, bl+2);
                mma16(acc[2*n0p+1], al, bh+2);
            }
        }
    }

    int rg1 = m0 + r0, rg2 = rg1 + 8;
    if (mode == 0) {
        float* G = (which == 0) ? g_Q : (which == 1) ? g_K : g_V;
        int b1 = rg1 >> 11, s1 = rg1 & 2047;
        int b2 = rg2 >> 11, s2 = rg2 & 2047;
        float* p1 = G + ((size_t)(b1*HH + hn)*SS + s1) * DK;
        float* p2 = G + ((size_t)(b2*HH + hn)*SS + s2) * DK;
        #pragma unroll
        for (int n0 = 0; n0 < 8; n0++) {
            int cn = n0*8 + 2*t4;
            *(float2*)&p1[cn] = make_float2(acc[n0][0], acc[n0][1]);
            *(float2*)&p2[cn] = make_float2(acc[n0][2], acc[n0][3]);
        }
    } else {
        #pragma unroll
        for (int n0 = 0; n0 < 8; n0++) {
            int cn = hn*64 + n0*8 + 2*t4;
            *(float2*)&outp[(size_t)rg1 * EE + cn] = make_float2(acc[n0][0], acc[n0][1]);
            *(float2*)&outp[(size_t)rg2 * EE + cn] = make_float2(acc[n0][2], acc[n0][3]);
        }
    }
}

// ---------------------------------------------------------------------------
// Flash attention, 3xBF16 + ldmatrix. grid=(S/128, H, B), block=256 (8 warps).
// 128 query rows per block; warp w owns rows [16w, 16w+16). Q hi/lo frags in
// registers (pre-scaled by 1/8). Per 64-key tile: V f32 prefetched to regs at
// loop top (LDG overlaps K staging + QK^T + softmax); converted/stored after
// softmax. Packed word stride 36.
// ---------------------------------------------------------------------------
#define KW 36
#define QR 128
// Layout words: Ss QR*68 | Kh,Kl 2*64*KW | Vh,Vl 2*64*KW | P2h,P2l 2*QR*KW | 3*QR
#define FLASH_SMEM ((QR*68 + 4*64*KW + 2*QR*KW + 3*QR) * 4)

__global__ __launch_bounds__(256) void flash_kernel(const int* __restrict__ mask)
{
    extern __shared__ char smraw[];
    float*    Ss  = (float*)smraw;              // [QR][68] fp32 scores
    unsigned* Kh  = (unsigned*)(Ss + QR*68);    // [64 key][KW]
    unsigned* Kl  = Kh  + 64*KW;
    unsigned* Vh  = Kl  + 64*KW;                // [64 dk][KW] (key-packed)
    unsigned* Vl  = Vh  + 64*KW;
    unsigned* P2h = Vl  + 64*KW;                // [QR q][KW] (Q staging, then P)
    unsigned* P2l = P2h + QR*KW;
    float* m_s    = (float*)(P2l + QR*KW);      // [QR]
    float* l_s    = m_s + QR;
    float* corr_s = l_s + QR;

    int qt = blockIdx.x, h = blockIdx.y, b = blockIdx.z;
    int t = threadIdx.x, w = t >> 5, l = t & 31;
    int t4 = l & 3;
    int g = l >> 2;
    int lj = l >> 3, lr = l & 7;
    int r0 = 16*w + g;

    const float* Qp = g_Q + ((size_t)(b*HH + h)*SS + qt*QR) * DK;
    const float* Kp = g_K + (size_t)(b*HH + h) * SS * DK;
    const float* Vp = g_V + (size_t)(b*HH + h) * SS * DK;
    const int*   Mp = mask + ((size_t)b*SS + qt*QR) * SS;

    int arow = 16*w + lr + (lj & 1) * 8;
    int acol_q = (lj >> 1) * 4;
    int brow_off = lr + (lj >> 1) * 8;
    int bcol_q = (lj & 1) * 4;

    // Stage Q (x 1/8) hi/lo packed into P2h/P2l, then pull fragments to regs.
    #pragma unroll
    for (int i = 0; i < 16; i++) {
        int idx = t + i * 256;
        int r = idx >> 5, k2 = idx & 31;
        float2 x = *(const float2*)&Qp[r*DK + 2*k2];
        split2(x.x * 0.125f, x.y * 0.125f, P2h[r*KW + k2], P2l[r*KW + k2]);
    }
    if (t < QR) { m_s[t] = -INFINITY; l_s[t] = 0.f; }
    __syncthreads();

    unsigned qfh[4][4], qfl[4][4];
    #pragma unroll
    for (int kc = 0; kc < 4; kc++) {
        ldsm_x4(qfh[kc], &P2h[arow*KW + kc*8 + acol_q]);
        ldsm_x4(qfl[kc], &P2l[arow*KW + kc*8 + acol_q]);
    }

    float acc[8][4] = {};

    // staging address components (256 threads, 64x32-word tiles: 8 chunks)
    int kr = t >> 5, kk2 = t & 31;          // K: row step 8
    int vd = t & 63, vk2 = t >> 6;          // V: key2 step 4

    for (int kt = 0; kt < SS/64; kt++) {
        __syncthreads();
        const float* Kt = Kp + (size_t)kt * 64 * DK;
        const float* Vt = Vp + (size_t)kt * 64 * DK;

        // V f32 prefetch into registers (consumed after softmax)
        float pv0[8], pv1[8];
        #pragma unroll
        for (int i = 0; i < 8; i++) {
            pv0[i] = Vt[(2*(vk2 + i*4))     * DK + vd];
            pv1[i] = Vt[(2*(vk2 + i*4) + 1) * DK + vd];
        }

        // K tile: [key][dk2], pack
        #pragma unroll
        for (int i = 0; i < 8; i++) {
            float2 x = *(const float2*)&Kt[(kr + i*8)*DK + 2*kk2];
            split2(x.x, x.y, Kh[(kr + i*8)*KW + kk2], Kl[(kr + i*8)*KW + kk2]);
        }
        __syncthreads();

        // ---- QK^T (3x bf16, ldmatrix B) ----
        float sacc[8][4] = {};
        #pragma unroll
        for (int kc = 0; kc < 4; kc++) {
            #pragma unroll
            for (int n0p = 0; n0p < 4; n0p++) {
                unsigned bh[4], bl[4];
                int br = (n0p*16 + brow_off)*KW + kc*8 + bcol_q;
                ldsm_x4(bh, &Kh[br]);
                ldsm_x4(bl, &Kl[br]);
                mma16(sacc[2*n0p],   qfh[kc], bh);
                mma16(sacc[2*n0p],   qfh[kc], bl);
                mma16(sacc[2*n0p],   qfl[kc], bh);
                mma16(sacc[2*n0p+1], qfh[kc], bh+2);
                mma16(sacc[2*n0p+1], qfh[kc], bl+2);
                mma16(sacc[2*n0p+1], qfl[kc], bh+2);
            }
        }
        #pragma unroll
        for (int n0 = 0; n0 < 8; n0++) {
            int cc = n0*8 + 2*t4;
            *(float2*)&Ss[r0*68 + cc]     = make_float2(sacc[n0][0], sacc[n0][1]);
            *(float2*)&Ss[(r0+8)*68 + cc] = make_float2(sacc[n0][2], sacc[n0][3]);
        }
        __syncwarp();

        // ---- masked online softmax (lane pair per row: 32 cols each) ----
        {
            int row = 16*w + (l >> 1);
            int j0 = (l & 1) * 32;
            const int* Mr = Mp + (size_t)row * SS + kt*64 + j0;
            float s[32];
            #pragma unroll
            for (int i = 0; i < 8; i++) {
                float4 v = *(const float4*)&Ss[row*68 + j0 + i*4];
                s[i*4] = v.x; s[i*4+1] = v.y; s[i*4+2] = v.z; s[i*4+3] = v.w;
            }
            #pragma unroll
            for (int i = 0; i < 8; i++) {
                int4 mm = *(const int4*)&Mr[i*4];
                s[i*4]   = mm.x ? s[i*4]   : -1e9f;
                s[i*4+1] = mm.y ? s[i*4+1] : -1e9f;
                s[i*4+2] = mm.z ? s[i*4+2] : -1e9f;
                s[i*4+3] = mm.w ? s[i*4+3] : -1e9f;
            }
            float mx = -INFINITY;
            #pragma unroll
            for (int j = 0; j < 32; j++) mx = fmaxf(mx, s[j]);
            mx = fmaxf(mx, __shfl_xor_sync(0xffffffffu, mx, 1));
            float mold = m_s[row];
            float mnew = fmaxf(mold, mx);
            float corr = __expf(mold - mnew);   // 0 on first tile (mold=-inf)
            float ls = 0.f;
            #pragma unroll
            for (int j = 0; j < 32; j++) {
                float p = __expf(s[j] - mnew);
                s[j] = p;
                ls += p;
            }
            ls += __shfl_xor_sync(0xffffffffu, ls, 1);
            int c0 = (l & 1) * 16;
            #pragma unroll
            for (int i = 0; i < 16; i++)
                split2(s[2*i], s[2*i+1], P2h[row*KW + c0 + i], P2l[row*KW + c0 + i]);
            m_s[row] = mnew;
            l_s[row] = l_s[row] * corr + ls;
            corr_s[row] = corr;
        }

        // V regs -> packed smem (Vh/Vl not read since loop-top sync)
        #pragma unroll
        for (int i = 0; i < 8; i++)
            split2(pv0[i], pv1[i], Vh[vd*KW + vk2 + i*4], Vl[vd*KW + vk2 + i*4]);
        __syncthreads();

        // ---- PV (3x bf16, ldmatrix A and B) ----
        float cr1 = corr_s[r0];
        float cr2 = corr_s[r0 + 8];
        #pragma unroll
        for (int n0 = 0; n0 < 8; n0++) {
            acc[n0][0] *= cr1; acc[n0][1] *= cr1;
            acc[n0][2] *= cr2; acc[n0][3] *= cr2;
        }
        #pragma unroll
        for (int kc = 0; kc < 4; kc++) {
            unsigned ah[4], al[4];
            ldsm_x4(ah, &P2h[arow*KW + kc*8 + acol_q]);
            ldsm_x4(al, &P2l[arow*KW + kc*8 + acol_q]);
            #pragma unroll
            for (int n0p = 0; n0p < 4; n0p++) {
                unsigned bh[4], bl[4];
                int br = (n0p*16 + brow_off)*KW + kc*8 + bcol_q;
                ldsm_x4(bh, &Vh[br]);
                ldsm_x4(bl, &Vl[br]);
                mma16(acc[2*n0p],   ah, bh);
                mma16(acc[2*n0p],   ah, bl);
                mma16(acc[2*n0p],   al, bh);
                mma16(acc[2*n0p+1], ah, bh+2);
                mma16(acc[2*n0p+1], ah, bl+2);
                mma16(acc[2*n0p+1], al, bh+2);
            }
        }
    }

    __syncwarp();
    float inv1 = 1.f / l_s[r0];
    float inv2 = 1.f / l_s[r0 + 8];
    int row1 = qt*QR + r0;
    float* Cb = g_C + (size_t)b * SS * EE + (size_t)h * DK;
    #pragma unroll
    for (int n0 = 0; n0 < 8; n0++) {
        int cc = n0*8 + 2*t4;
        *(float2*)&Cb[(size_t)row1 * EE + cc] =
            make_float2(acc[n0][0]*inv1, acc[n0][1]*inv1);
        *(float2*)&Cb[(size_t)(row1+8) * EE + cc] =
            make_float2(acc[n0][2]*inv2, acc[n0][3]*inv2);
    }
}

// ---------------------------------------------------------------------------
extern "C" void kernel_launch(void* const* d_in, const int* in_sizes, int n_in,
                              void* d_out, int out_size)
{
    const float* q    = (const float*)d_in[0];
    const float* k    = (const float*)d_in[1];
    const float* v    = (const float*)d_in[2];
    const int*   mask = (const int*)  d_in[3];
    const float* Wq   = (const float*)d_in[4];
    const float* Wk   = (const float*)d_in[5];
    const float* Wv   = (const float*)d_in[6];
    const float* W    = (const float*)d_in[7];
    float* out = (float*)d_out;

    cudaFuncSetAttribute(flash_kernel,
                         cudaFuncAttributeMaxDynamicSharedMemorySize, FLASH_SMEM);

    // QKV projections (3xBF16 tensor cores, pipelined)
    gemm_kernel<<<dim3((BB*SS)/64, HH, 3), 128>>>(q, k, v, Wq, Wk, Wv, nullptr, nullptr, 0);

    // Flash attention (3xBF16 tensor cores, 128-row tiles)
    flash_kernel<<<dim3(SS/QR, HH, BB), 256, FLASH_SMEM>>>(mask);

    // Output projection (3xBF16 tensor cores, pipelined)
    gemm_kernel<<<dim3((BB*SS)/64, EE/64, 1), 128>>>(nullptr, nullptr, nullptr,
                                                     nullptr, nullptr, nullptr, W, out, 1);
}

// round 11
// speedup vs baseline: 1.4599x; 1.2320x over previous
#include <cuda_runtime.h>
#include <cuda_bf16.h>
#include <math.h>

#define BB 2
#define SS 2048
#define EE 768
#define HH 12
#define DK 64

// Scratch (allocation-free: __device__ globals)
__device__ float g_Q[BB*HH*SS*DK];   // [B,H,S,Dk]
__device__ float g_K[BB*HH*SS*DK];
__device__ float g_V[BB*HH*SS*DK];
__device__ float g_C[BB*SS*EE];      // concat [B,S,H*Dk]

// Split two floats into packed bf16x2 hi and lo words (lo = residual).
__device__ __forceinline__ void split2(float x0, float x1, unsigned& hi, unsigned& lo) {
    __nv_bfloat162 h2 = __floats2bfloat162_rn(x0, x1);
    float h0 = __bfloat162float(__low2bfloat16(h2));
    float h1 = __bfloat162float(__high2bfloat16(h2));
    __nv_bfloat162 l2 = __floats2bfloat162_rn(x0 - h0, x1 - h1);
    hi = *reinterpret_cast<unsigned*>(&h2);
    lo = *reinterpret_cast<unsigned*>(&l2);
}

// D += A*B, m16n8k16 bf16, A row-major, B col-major, f32 accumulate.
__device__ __forceinline__ void mma16(float c[4], const unsigned a[4], const unsigned* b) {
    asm volatile(
        "mma.sync.aligned.m16n8k16.row.col.f32.bf16.bf16.f32 "
        "{%0,%1,%2,%3},{%4,%5,%6,%7},{%8,%9},{%0,%1,%2,%3};"
        : "+f"(c[0]), "+f"(c[1]), "+f"(c[2]), "+f"(c[3])
        : "r"(a[0]), "r"(a[1]), "r"(a[2]), "r"(a[3]), "r"(b[0]), "r"(b[1]));
}

// ldmatrix x4: 4 8x8 b16 matrices; each lane supplies one row address.
__device__ __forceinline__ void ldsm_x4(unsigned r[4], const void* p) {
    unsigned addr = (unsigned)__cvta_generic_to_shared(p);
    asm volatile("ldmatrix.sync.aligned.m8n8.x4.shared.b16 {%0,%1,%2,%3}, [%4];"
                 : "=r"(r[0]), "=r"(r[1]), "=r"(r[2]), "=r"(r[3]) : "r"(addr));
}

// ---------------------------------------------------------------------------
// 3xBF16 GEMM, 64x64 tile, BK=32, 128 threads, register-prefetch pipelined.
// mode 0: QKV projections. grid=(M/64, H, 3).
// mode 1: out projection. grid=(M/64, EE/64, 1).
// ---------------------------------------------------------------------------
#define GW 20

__global__ __launch_bounds__(128) void gemm_kernel(
    const float* __restrict__ Xq, const float* __restrict__ Xk, const float* __restrict__ Xv,
    const float* __restrict__ Wq, const float* __restrict__ Wk, const float* __restrict__ Wv,
    const float* __restrict__ Wo, float* __restrict__ outp, int mode)
{
    __shared__ unsigned Ah[64*GW], Al[64*GW];   // [row][k2]
    __shared__ unsigned Bh[64*GW], Bl[64*GW];   // [n][k2]

    int bx = blockIdx.x, hn = blockIdx.y, which = blockIdx.z;
    int t = threadIdx.x, w = t >> 5, l = t & 31;
    int t4 = l & 3;
    int g = l >> 2;
    int lj = l >> 3, lr = l & 7;
    int m0 = bx * 64;

    const float* A;
    const float* Bw;
    int ldb;
    if (mode == 0) {
        A = (which == 0) ? Xq : (which == 1) ? Xk : Xv;
        const float* Ws = (which == 0) ? Wq : (which == 1) ? Wk : Wv;
        Bw = Ws + (size_t)hn * EE * DK;
        ldb = DK;
    } else {
        A = g_C;
        Bw = Wo + hn * 64;
        ldb = EE;
    }

    float acc[8][4] = {};
    int r0 = 16*w + g;

    int arow = 16*w + lr + (lj & 1) * 8;
    int acol_q = (lj >> 1) * 4;
    int brow_off = lr + (lj >> 1) * 8;
    int bcol_q = (lj & 1) * 4;

    // addressing for staging
    int ar = t >> 4, ak2 = t & 15;          // with i*8 row step
    int bn = t & 63, bk2 = t >> 6;          // with i*2 k2 step

    float2 pa[8];
    float  pb0[8], pb1[8];

    // prefetch k0 = 0
    #pragma unroll
    for (int i = 0; i < 8; i++)
        pa[i] = *(const float2*)&A[(size_t)(m0 + ar + i*8) * EE + 2*ak2];
    #pragma unroll
    for (int i = 0; i < 8; i++) {
        pb0[i] = Bw[(size_t)(2*(bk2 + i*2))     * ldb + bn];
        pb1[i] = Bw[(size_t)(2*(bk2 + i*2) + 1) * ldb + bn];
    }

    for (int k0 = 0; k0 < EE; k0 += 32) {
        __syncthreads();
        #pragma unroll
        for (int i = 0; i < 8; i++)
            split2(pa[i].x, pa[i].y, Ah[(ar + i*8)*GW + ak2], Al[(ar + i*8)*GW + ak2]);
        #pragma unroll
        for (int i = 0; i < 8; i++)
            split2(pb0[i], pb1[i], Bh[bn*GW + bk2 + i*2], Bl[bn*GW + bk2 + i*2]);
        __syncthreads();

        if (k0 + 32 < EE) {
            int kn = k0 + 32;
            #pragma unroll
            for (int i = 0; i < 8; i++)
                pa[i] = *(const float2*)&A[(size_t)(m0 + ar + i*8) * EE + kn + 2*ak2];
            #pragma unroll
            for (int i = 0; i < 8; i++) {
                pb0[i] = Bw[(size_t)(kn + 2*(bk2 + i*2))     * ldb + bn];
                pb1[i] = Bw[(size_t)(kn + 2*(bk2 + i*2) + 1) * ldb + bn];
            }
        }

        #pragma unroll
        for (int kc = 0; kc < 2; kc++) {
            unsigned ah[4], al[4];
            ldsm_x4(ah, &Ah[arow*GW + kc*8 + acol_q]);
            ldsm_x4(al, &Al[arow*GW + kc*8 + acol_q]);
            #pragma unroll
            for (int n0p = 0; n0p < 4; n0p++) {
                unsigned bh[4], bl[4];
                int br = (n0p*16 + brow_off)*GW + kc*8 + bcol_q;
                ldsm_x4(bh, &Bh[br]);
                ldsm_x4(bl, &Bl[br]);
                mma16(acc[2*n0p],   ah, bh);
                mma16(acc[2*n0p],   ah, bl);
                mma16(acc[2*n0p],   al, bh);
                mma16(acc[2*n0p+1], ah, bh+2);
                mma16(acc[2*n0p+1], ah, bl+2);
                mma16(acc[2*n0p+1], al, bh+2);
            }
        }
    }

    int rg1 = m0 + r0, rg2 = rg1 + 8;
    if (mode == 0) {
        float* G = (which == 0) ? g_Q : (which == 1) ? g_K : g_V;
        int b1 = rg1 >> 11, s1 = rg1 & 2047;
        int b2 = rg2 >> 11, s2 = rg2 & 2047;
        float* p1 = G + ((size_t)(b1*HH + hn)*SS + s1) * DK;
        float* p2 = G + ((size_t)(b2*HH + hn)*SS + s2) * DK;
        #pragma unroll
        for (int n0 = 0; n0 < 8; n0++) {
            int cn = n0*8 + 2*t4;
            *(float2*)&p1[cn] = make_float2(acc[n0][0], acc[n0][1]);
            *(float2*)&p2[cn] = make_float2(acc[n0][2], acc[n0][3]);
        }
    } else {
        #pragma unroll
        for (int n0 = 0; n0 < 8; n0++) {
            int cn = hn*64 + n0*8 + 2*t4;
            *(float2*)&outp[(size_t)rg1 * EE + cn] = make_float2(acc[n0][0], acc[n0][1]);
            *(float2*)&outp[(size_t)rg2 * EE + cn] = make_float2(acc[n0][2], acc[n0][3]);
        }
    }
}

// ---------------------------------------------------------------------------
// Flash attention, 3xBF16 + ldmatrix, register-resident softmax.
// grid=(S/128, H, B), block=256 (8 warps); warp w owns q rows [16w,16w+16).
// The QK^T C-fragment layout IS the PV A-fragment layout, so scores never
// touch smem: mask/max/exp/sum happen on registers (shfl over the t4 quad)
// and P is split hi/lo directly into mma fragments. Smem = K/V tiles only
// (36.9KB static) -> 2 CTAs/SM.
// ---------------------------------------------------------------------------
#define KW 36
#define QR 128

__global__ __launch_bounds__(256, 2) void flash_kernel(const int* __restrict__ mask)
{
    __shared__ unsigned SB[4*64*KW];            // Kh | Kl | Vh | Vl (2304 each)
    unsigned* Kh = SB;                          // [64 key][KW]
    unsigned* Kl = SB + 64*KW;
    unsigned* Vh = SB + 2*64*KW;                // [64 dk][KW] (key-packed)
    unsigned* Vl = SB + 3*64*KW;

    int qt = blockIdx.x, h = blockIdx.y, b = blockIdx.z;
    int t = threadIdx.x, w = t >> 5, l = t & 31;
    int t4 = l & 3;
    int g = l >> 2;
    int lj = l >> 3, lr = l & 7;
    int r0 = 16*w + g;

    const float* Qp = g_Q + ((size_t)(b*HH + h)*SS + qt*QR) * DK;
    const float* Kp = g_K + (size_t)(b*HH + h) * SS * DK;
    const float* Vp = g_V + (size_t)(b*HH + h) * SS * DK;
    const int*   Mp = mask + ((size_t)b*SS + qt*QR) * SS;

    int arow = 16*w + lr + (lj & 1) * 8;
    int acol_q = (lj >> 1) * 4;
    int brow_off = lr + (lj >> 1) * 8;
    int bcol_q = (lj & 1) * 4;

    // Stage Q (x 1/8) hi/lo into SB (Qh = SB[0..4608), Ql = SB[4608..9216)),
    // stride KW; pull fragments to regs; loop-top sync protects reuse.
    #pragma unroll
    for (int i = 0; i < 16; i++) {
        int idx = t + i * 256;
        int r = idx >> 5, k2 = idx & 31;
        float2 x = *(const float2*)&Qp[r*DK + 2*k2];
        split2(x.x * 0.125f, x.y * 0.125f, SB[r*KW + k2], SB[QR*KW + r*KW + k2]);
    }
    __syncthreads();

    unsigned qfh[4][4], qfl[4][4];
    #pragma unroll
    for (int kc = 0; kc < 4; kc++) {
        ldsm_x4(qfh[kc], &SB[arow*KW + kc*8 + acol_q]);
        ldsm_x4(qfl[kc], &SB[QR*KW + arow*KW + kc*8 + acol_q]);
    }

    float acc[8][4] = {};
    float m1 = -INFINITY, m2 = -INFINITY, l1 = 0.f, l2 = 0.f;

    // staging address components
    int kr = t >> 5, kk2 = t & 31;          // K: rows kr + i*8
    int vd = t & 63, vk2 = t >> 6;          // V: d = vd, key2 = vk2 + i*4

    for (int kt = 0; kt < SS/64; kt++) {
        __syncthreads();
        const float* Kt = Kp + (size_t)kt * 64 * DK;
        const float* Vt = Vp + (size_t)kt * 64 * DK;

        // K tile: [key][dk2]
        #pragma unroll
        for (int i = 0; i < 8; i++) {
            float2 x = *(const float2*)&Kt[(kr + i*8)*DK + 2*kk2];
            split2(x.x, x.y, Kh[(kr + i*8)*KW + kk2], Kl[(kr + i*8)*KW + kk2]);
        }
        // V tile transposed: [dk][key2]
        #pragma unroll
        for (int i = 0; i < 8; i++) {
            float x0 = Vt[(2*(vk2 + i*4))     * DK + vd];
            float x1 = Vt[(2*(vk2 + i*4) + 1) * DK + vd];
            split2(x0, x1, Vh[vd*KW + vk2 + i*4], Vl[vd*KW + vk2 + i*4]);
        }
        __syncthreads();

        // ---- QK^T (3x bf16, ldmatrix B) ----
        float sacc[8][4] = {};
        #pragma unroll
        for (int kc = 0; kc < 4; kc++) {
            #pragma unroll
            for (int n0p = 0; n0p < 4; n0p++) {
                unsigned bh[4], bl[4];
                int br = (n0p*16 + brow_off)*KW + kc*8 + bcol_q;
                ldsm_x4(bh, &Kh[br]);
                ldsm_x4(bl, &Kl[br]);
                mma16(sacc[2*n0p],   qfh[kc], bh);
                mma16(sacc[2*n0p],   qfh[kc], bl);
                mma16(sacc[2*n0p],   qfl[kc], bh);
                mma16(sacc[2*n0p+1], qfh[kc], bh+2);
                mme_pad: ;
                mma16(sacc[2*n0p+1], qfh[kc], bl+2);
                mma16(sacc[2*n0p+1], qfl[kc], bh+2);
            }
        }

        // ---- mask + online softmax, all in registers ----
        const int* Mr1 = Mp + (size_t)r0 * SS + kt*64;
        const int* Mr2 = Mp + (size_t)(r0 + 8) * SS + kt*64;
        #pragma unroll
        for (int n0 = 0; n0 < 8; n0++) {
            int2 ma = *(const int2*)&Mr1[n0*8 + 2*t4];
            int2 mb = *(const int2*)&Mr2[n0*8 + 2*t4];
            sacc[n0][0] = ma.x ? sacc[n0][0] : -1e9f;
            sacc[n0][1] = ma.y ? sacc[n0][1] : -1e9f;
            sacc[n0][2] = mb.x ? sacc[n0][2] : -1e9f;
            sacc[n0][3] = mb.y ? sacc[n0][3] : -1e9f;
        }
        float mx1 = -INFINITY, mx2 = -INFINITY;
        #pragma unroll
        for (int n0 = 0; n0 < 8; n0++) {
            mx1 = fmaxf(mx1, fmaxf(sacc[n0][0], sacc[n0][1]));
            mx2 = fmaxf(mx2, fmaxf(sacc[n0][2], sacc[n0][3]));
        }
        mx1 = fmaxf(mx1, __shfl_xor_sync(0xffffffffu, mx1, 1));
        mx1 = fmaxf(mx1, __shfl_xor_sync(0xffffffffu, mx1, 2));
        mx2 = fmaxf(mx2, __shfl_xor_sync(0xffffffffu, mx2, 1));
        mx2 = fmaxf(mx2, __shfl_xor_sync(0xffffffffu, mx2, 2));
        float mn1 = fmaxf(m1, mx1), mn2 = fmaxf(m2, mx2);
        float cr1 = __expf(m1 - mn1), cr2 = __expf(m2 - mn2);
        float ls1 = 0.f, ls2 = 0.f;
        #pragma unroll
        for (int n0 = 0; n0 < 8; n0++) {
            float p0 = __expf(sacc[n0][0] - mn1);
            float p1 = __expf(sacc[n0][1] - mn1);
            float p2 = __expf(sacc[n0][2] - mn2);
            float p3 = __expf(sacc[n0][3] - mn2);
            ls1 += p0 + p1; ls2 += p2 + p3;
            sacc[n0][0] = p0; sacc[n0][1] = p1;
            sacc[n0][2] = p2; sacc[n0][3] = p3;
        }
        ls1 += __shfl_xor_sync(0xffffffffu, ls1, 1);
        ls1 += __shfl_xor_sync(0xffffffffu, ls1, 2);
        ls2 += __shfl_xor_sync(0xffffffffu, ls2, 1);
        ls2 += __shfl_xor_sync(0xffffffffu, ls2, 2);
        m1 = mn1; m2 = mn2;
        l1 = l1 * cr1 + ls1;
        l2 = l2 * cr2 + ls2;

        // ---- PV (3x bf16): P fragments built from sacc in registers ----
        #pragma unroll
        for (int n0 = 0; n0 < 8; n0++) {
            acc[n0][0] *= cr1; acc[n0][1] *= cr1;
            acc[n0][2] *= cr2; acc[n0][3] *= cr2;
        }
        #pragma unroll
        for (int kc = 0; kc < 4; kc++) {
            unsigned ah[4], al[4];
            split2(sacc[2*kc][0],   sacc[2*kc][1],   ah[0], al[0]);
            split2(sacc[2*kc][2],   sacc[2*kc][3],   ah[1], al[1]);
            split2(sacc[2*kc+1][0], sacc[2*kc+1][1], ah[2], al[2]);
            split2(sacc[2*kc+1][2], sacc[2*kc+1][3], ah[3], al[3]);
            #pragma unroll
            for (int n0p = 0; n0p < 4; n0p++) {
                unsigned bh[4], bl[4];
                int br = (n0p*16 + brow_off)*KW + kc*8 + bcol_q;
                ldsm_x4(bh, &Vh[br]);
                ldsm_x4(bl, &Vl[br]);
                mma16(acc[2*n0p],   ah, bh);
                mma16(acc[2*n0p],   ah, bl);
                mma16(acc[2*n0p],   al, bh);
                mma16(acc[2*n0p+1], ah, bh+2);
                mma16(acc[2*n0p+1], ah, bl+2);
                mma16(acc[2*n0p+1], al, bh+2);
            }
        }
    }

    float inv1 = 1.f / l1;
    float inv2 = 1.f / l2;
    int row1 = qt*QR + r0;
    float* Cb = g_C + (size_t)b * SS * EE + (size_t)h * DK;
    #pragma unroll
    for (int n0 = 0; n0 < 8; n0++) {
        int cc = n0*8 + 2*t4;
        *(float2*)&Cb[(size_t)row1 * EE + cc] =
            make_float2(acc[n0][0]*inv1, acc[n0][1]*inv1);
        *(float2*)&Cb[(size_t)(row1+8) * EE + cc] =
            make_float2(acc[n0][2]*inv2, acc[n0][3]*inv2);
    }
}

// ---------------------------------------------------------------------------
extern "C" void kernel_launch(void* const* d_in, const int* in_sizes, int n_in,
                              void* d_out, int out_size)
{
    const float* q    = (const float*)d_in[0];
    const float* k    = (const float*)d_in[1];
    const float* v    = (const float*)d_in[2];
    const int*   mask = (const int*)  d_in[3];
    const float* Wq   = (const float*)d_in[4];
    const float* Wk   = (const float*)d_in[5];
    const float* Wv   = (const float*)d_in[6];
    const float* W    = (const float*)d_in[7];
    float* out = (float*)d_out;

    // QKV projections (3xBF16 tensor cores, pipelined)
    gemm_kernel<<<dim3((BB*SS)/64, HH, 3), 128>>>(q, k, v, Wq, Wk, Wv, nullptr, nullptr, 0);

    // Flash attention (3xBF16, register-resident softmax, 2 CTAs/SM)
    flash_kernel<<<dim3(SS/QR, HH, BB), 256>>>(mask);

    // Output projection (3xBF16 tensor cores, pipelined)
    gemm_kernel<<<dim3((BB*SS)/64, EE/64, 1), 128>>>(nullptr, nullptr, nullptr,
                                                     nullptr, nullptr, nullptr, W, out, 1);
}

// round 12
// speedup vs baseline: 1.5077x; 1.0327x over previous
#include <cuda_runtime.h>
#include <cuda_bf16.h>
#include <math.h>

#define BB 2
#define SS 2048
#define EE 768
#define HH 12
#define DK 64

// Scratch (allocation-free: __device__ globals)
__device__ float g_Q[BB*HH*SS*DK];   // [B,H,S,Dk]
__device__ float g_K[BB*HH*SS*DK];
__device__ float g_V[BB*HH*SS*DK];
__device__ float g_C[BB*SS*EE];      // concat [B,S,H*Dk]

// Split two floats into packed bf16x2 hi and lo words (lo = residual).
__device__ __forceinline__ void split2(float x0, float x1, unsigned& hi, unsigned& lo) {
    __nv_bfloat162 h2 = __floats2bfloat162_rn(x0, x1);
    float h0 = __bfloat162float(__low2bfloat16(h2));
    float h1 = __bfloat162float(__high2bfloat16(h2));
    __nv_bfloat162 l2 = __floats2bfloat162_rn(x0 - h0, x1 - h1);
    hi = *reinterpret_cast<unsigned*>(&h2);
    lo = *reinterpret_cast<unsigned*>(&l2);
}

// D += A*B, m16n8k16 bf16, A row-major, B col-major, f32 accumulate.
__device__ __forceinline__ void mma16(float c[4], const unsigned a[4], const unsigned* b) {
    asm volatile(
        "mma.sync.aligned.m16n8k16.row.col.f32.bf16.bf16.f32 "
        "{%0,%1,%2,%3},{%4,%5,%6,%7},{%8,%9},{%0,%1,%2,%3};"
        : "+f"(c[0]), "+f"(c[1]), "+f"(c[2]), "+f"(c[3])
        : "r"(a[0]), "r"(a[1]), "r"(a[2]), "r"(a[3]), "r"(b[0]), "r"(b[1]));
}

// ldmatrix x4: 4 8x8 b16 matrices; each lane supplies one row address.
__device__ __forceinline__ void ldsm_x4(unsigned r[4], const void* p) {
    unsigned addr = (unsigned)__cvta_generic_to_shared(p);
    asm volatile("ldmatrix.sync.aligned.m8n8.x4.shared.b16 {%0,%1,%2,%3}, [%4];"
                 : "=r"(r[0]), "=r"(r[1]), "=r"(r[2]), "=r"(r[3]) : "r"(addr));
}

// ---------------------------------------------------------------------------
// 3xBF16 GEMM, 128x128 tile, BK=32, 256 threads (8 warps x 16 rows x 128 cols),
// register-prefetch pipelined.
// mode 0: fused QKV: X[4096,768] @ Wall[768, 2304]. grid=(32, 18).
//         column ng -> which=ng/768, head=(ng%768)/64, d=ng%64.
// mode 1: out projection: g_C @ Wo. grid=(32, 6).
// ---------------------------------------------------------------------------
#define GW 20

__global__ __launch_bounds__(256) void gemm_kernel(
    const float* __restrict__ Xq, const float* __restrict__ Xk, const float* __restrict__ Xv,
    const float* __restrict__ Wq, const float* __restrict__ Wk, const float* __restrict__ Wv,
    const float* __restrict__ Wo, float* __restrict__ outp, int mode)
{
    __shared__ unsigned Ah[128*GW], Al[128*GW];   // [row][k2]
    __shared__ unsigned Bh[128*GW], Bl[128*GW];   // [n][k2]

    int bx = blockIdx.x, by = blockIdx.y;
    int t = threadIdx.x, w = t >> 5, l = t & 31;
    int t4 = l & 3;
    int g = l >> 2;
    int lj = l >> 3, lr = l & 7;
    int m0 = bx * 128;
    int n0 = by * 128;

    // A source (mode 0: which = n0/768 selects q/k/v input)
    const float* A;
    const float* Bbase;   // start of this tile's B columns in gmem
    int ldb;              // row stride of B in elements
    if (mode == 0) {
        int which = n0 / EE;
        int rem = n0 - which * EE;        // 0..704, multiple of 128
        A = (which == 0) ? Xq : (which == 1) ? Xk : Xv;
        const float* Ws = (which == 0) ? Wq : (which == 1) ? Wk : Wv;
        // local n in [0,128): head = (rem+n)/64, d = (rem+n)%64
        Bbase = Ws + (size_t)(rem / 64) * EE * DK;  // first head of the pair
        ldb = DK;
    } else {
        A = g_C;
        Bbase = Wo + n0;
        ldb = EE;
    }

    float acc[16][4] = {};
    int r0 = 16*w + g;

    int arow = 16*w + lr + (lj & 1) * 8;
    int acol_q = (lj >> 1) * 4;
    int brow_off = lr + (lj >> 1) * 8;
    int bcol_q = (lj & 1) * 4;

    // staging address components: 8 chunks of 256
    int ar = t >> 4, ak2 = t & 15;            // A: rows ar + i*16
    int bn = t & 127, bk2 = t >> 7;           // B: n = bn, k2 = bk2 + i*2

    // per-thread gmem B column offset (mode 0: head-split within tile)
    size_t bcol_off;
    if (mode == 0) {
        int hsel = bn >> 6;                   // 0 or 1 within the 2-head tile
        bcol_off = (size_t)hsel * EE * DK + (bn & 63);
    } else {
        bcol_off = bn;
    }

    float2 pa[8];
    float  pb0[8], pb1[8];

    // prefetch k0 = 0
    #pragma unroll
    for (int i = 0; i < 8; i++)
        pa[i] = *(const float2*)&A[(size_t)(m0 + ar + i*16) * EE + 2*ak2];
    #pragma unroll
    for (int i = 0; i < 8; i++) {
        pb0[i] = Bbase[(size_t)(2*(bk2 + i*2))     * ldb + bcol_off];
        pb1[i] = Bbase[(size_t)(2*(bk2 + i*2) + 1) * ldb + bcol_off];
    }

    for (int k0 = 0; k0 < EE; k0 += 32) {
        __syncthreads();
        #pragma unroll
        for (int i = 0; i < 8; i++)
            split2(pa[i].x, pa[i].y, Ah[(ar + i*16)*GW + ak2], Al[(ar + i*16)*GW + ak2]);
        #pragma unroll
        for (int i = 0; i < 8; i++)
            split2(pb0[i], pb1[i], Bh[bn*GW + bk2 + i*2], Bl[bn*GW + bk2 + i*2]);
        __syncthreads();

        if (k0 + 32 < EE) {
            int kn = k0 + 32;
            #pragma unroll
            for (int i = 0; i < 8; i++)
                pa[i] = *(const float2*)&A[(size_t)(m0 + ar + i*16) * EE + kn + 2*ak2];
            #pragma unroll
            for (int i = 0; i < 8; i++) {
                pb0[i] = Bbase[(size_t)(kn + 2*(bk2 + i*2))     * ldb + bcol_off];
                pb1[i] = Bbase[(size_t)(kn + 2*(bk2 + i*2) + 1) * ldb + bcol_off];
            }
        }

        #pragma unroll
        for (int kc = 0; kc < 2; kc++) {
            unsigned ah[4], al[4];
            ldsm_x4(ah, &Ah[arow*GW + kc*8 + acol_q]);
            ldsm_x4(al, &Al[arow*GW + kc*8 + acol_q]);
            #pragma unroll
            for (int n0p = 0; n0p < 8; n0p++) {
                unsigned bh[4], bl[4];
                int br = (n0p*16 + brow_off)*GW + kc*8 + bcol_q;
                ldsm_x4(bh, &Bh[br]);
                ldsm_x4(bl, &Bl[br]);
                mma16(acc[2*n0p],   ah, bh);
                mma16(acc[2*n0p],   ah, bl);
                mma16(acc[2*n0p],   al, bh);
                mma16(acc[2*n0p+1], ah, bh+2);
                mma16(acc[2*n0p+1], ah, bl+2);
                mma16(acc[2*n0p+1], al, bh+2);
            }
        }
    }

    // Epilogue: lane covers rows r0, r0+8 (+m0); cols n0 + nb*8 + 2*t4.
    int rg1 = m0 + r0, rg2 = rg1 + 8;
    if (mode == 0) {
        int which = n0 / EE;
        int rem = n0 - which * EE;
        float* G = (which == 0) ? g_Q : (which == 1) ? g_K : g_V;
        int b1 = rg1 >> 11, s1 = rg1 & 2047;
        int b2 = rg2 >> 11, s2 = rg2 & 2047;
        #pragma unroll
        for (int nb = 0; nb < 16; nb++) {
            int nloc = nb*8 + 2*t4;                 // 0..126
            int head = (rem + nloc) >> 6;
            int d = nloc & 63;
            float* p1 = G + ((size_t)(b1*HH + head)*SS + s1) * DK + d;
            float* p2 = G + ((size_t)(b2*HH + head)*SS + s2) * DK + d;
            *(float2*)p1 = make_float2(acc[nb][0], acc[nb][1]);
            *(float2*)p2 = make_float2(acc[nb][2], acc[nb][3]);
        }
    } else {
        #pragma unroll
        for (int nb = 0; nb < 16; nb++) {
            int cn = n0 + nb*8 + 2*t4;
            *(float2*)&outp[(size_t)rg1 * EE + cn] = make_float2(acc[nb][0], acc[nb][1]);
            *(float2*)&outp[(size_t)rg2 * EE + cn] = make_float2(acc[nb][2], acc[nb][3]);
        }
    }
}

// ---------------------------------------------------------------------------
// Flash attention, 3xBF16 + ldmatrix, register-resident softmax.
// grid=(S/128, H, B), block=256 (8 warps); warp w owns q rows [16w,16w+16).
// The QK^T C-fragment layout IS the PV A-fragment layout, so scores never
// touch smem: mask/max/exp/sum happen on registers (shfl over the t4 quad)
// and P is split hi/lo directly into mma fragments. Smem = K/V tiles only
// (36.9KB static) -> 2 CTAs/SM.
// ---------------------------------------------------------------------------
#define KW 36
#define QR 128

__global__ __launch_bounds__(256, 2) void flash_kernel(const int* __restrict__ mask)
{
    __shared__ unsigned SB[4*64*KW];            // Kh | Kl | Vh | Vl (2304 each)
    unsigned* Kh = SB;                          // [64 key][KW]
    unsigned* Kl = SB + 64*KW;
    unsigned* Vh = SB + 2*64*KW;                // [64 dk][KW] (key-packed)
    unsigned* Vl = SB + 3*64*KW;

    int qt = blockIdx.x, h = blockIdx.y, b = blockIdx.z;
    int t = threadIdx.x, w = t >> 5, l = t & 31;
    int t4 = l & 3;
    int g = l >> 2;
    int lj = l >> 3, lr = l & 7;
    int r0 = 16*w + g;

    const float* Qp = g_Q + ((size_t)(b*HH + h)*SS + qt*QR) * DK;
    const float* Kp = g_K + (size_t)(b*HH + h) * SS * DK;
    const float* Vp = g_V + (size_t)(b*HH + h) * SS * DK;
    const int*   Mp = mask + ((size_t)b*SS + qt*QR) * SS;

    int arow = 16*w + lr + (lj & 1) * 8;
    int acol_q = (lj >> 1) * 4;
    int brow_off = lr + (lj >> 1) * 8;
    int bcol_q = (lj & 1) * 4;

    // Stage Q (x 1/8) hi/lo into SB, stride KW; pull fragments to regs.
    #pragma unroll
    for (int i = 0; i < 16; i++) {
        int idx = t + i * 256;
        int r = idx >> 5, k2 = idx & 31;
        float2 x = *(const float2*)&Qp[r*DK + 2*k2];
        split2(x.x * 0.125f, x.y * 0.125f, SB[r*KW + k2], SB[QR*KW + r*KW + k2]);
    }
    __syncthreads();

    unsigned qfh[4][4], qfl[4][4];
    #pragma unroll
    for (int kc = 0; kc < 4; kc++) {
        ldsm_x4(qfh[kc], &SB[arow*KW + kc*8 + acol_q]);
        ldsm_x4(qfl[kc], &SB[QR*KW + arow*KW + kc*8 + acol_q]);
    }

    float acc[8][4] = {};
    float m1 = -INFINITY, m2 = -INFINITY, l1 = 0.f, l2 = 0.f;

    // staging address components
    int kr = t >> 5, kk2 = t & 31;          // K: rows kr + i*8
    int vd = t & 63, vk2 = t >> 6;          // V: d = vd, key2 = vk2 + i*4

    for (int kt = 0; kt < SS/64; kt++) {
        __syncthreads();
        const float* Kt = Kp + (size_t)kt * 64 * DK;
        const float* Vt = Vp + (size_t)kt * 64 * DK;

        // K tile: [key][dk2]
        #pragma unroll
        for (int i = 0; i < 8; i++) {
            float2 x = *(const float2*)&Kt[(kr + i*8)*DK + 2*kk2];
            split2(x.x, x.y, Kh[(kr + i*8)*KW + kk2], Kl[(kr + i*8)*KW + kk2]);
        }
        // V tile transposed: [dk][key2]
        #pragma unroll
        for (int i = 0; i < 8; i++) {
            float x0 = Vt[(2*(vk2 + i*4))     * DK + vd];
            float x1 = Vt[(2*(vk2 + i*4) + 1) * DK + vd];
            split2(x0, x1, Vh[vd*KW + vk2 + i*4], Vl[vd*KW + vk2 + i*4]);
        }
        __syncthreads();

        // ---- QK^T (3x bf16, ldmatrix B) ----
        float sacc[8][4] = {};
        #pragma unroll
        for (int kc = 0; kc < 4; kc++) {
            #pragma unroll
            for (int n0p = 0; n0p < 4; n0p++) {
                unsigned bh[4], bl[4];
                int br = (n0p*16 + brow_off)*KW + kc*8 + bcol_q;
                ldsm_x4(bh, &Kh[br]);
                ldsm_x4(bl, &Kl[br]);
                mma16(sacc[2*n0p],   qfh[kc], bh);
                mma16(sacc[2*n0p],   qfh[kc], bl);
                mma16(sacc[2*n0p],   qfl[kc], bh);
                mma16(sacc[2*n0p+1], qfh[kc], bh+2);
                mma16(sacc[2*n0p+1], qfh[kc], bl+2);
                mma16(sacc[2*n0p+1], qfl[kc], bh+2);
            }
        }

        // ---- mask + online softmax, all in registers ----
        const int* Mr1 = Mp + (size_t)r0 * SS + kt*64;
        const int* Mr2 = Mp + (size_t)(r0 + 8) * SS + kt*64;
        #pragma unroll
        for (int n0 = 0; n0 < 8; n0++) {
            int2 ma = *(const int2*)&Mr1[n0*8 + 2*t4];
            int2 mb = *(const int2*)&Mr2[n0*8 + 2*t4];
            sacc[n0][0] = ma.x ? sacc[n0][0] : -1e9f;
            sacc[n0][1] = ma.y ? sacc[n0][1] : -1e9f;
            sacc[n0][2] = mb.x ? sacc[n0][2] : -1e9f;
            sacc[n0][3] = mb.y ? sacc[n0][3] : -1e9f;
        }
        float mx1 = -INFINITY, mx2 = -INFINITY;
        #pragma unroll
        for (int n0 = 0; n0 < 8; n0++) {
            mx1 = fmaxf(mx1, fmaxf(sacc[n0][0], sacc[n0][1]));
            mx2 = fmaxf(mx2, fmaxf(sacc[n0][2], sacc[n0][3]));
        }
        mx1 = fmaxf(mx1, __shfl_xor_sync(0xffffffffu, mx1, 1));
        mx1 = fmaxf(mx1, __shfl_xor_sync(0xffffffffu, mx1, 2));
        mx2 = fmaxf(mx2, __shfl_xor_sync(0xffffffffu, mx2, 1));
        mx2 = fmaxf(mx2, __shfl_xor_sync(0xffffffffu, mx2, 2));
        float mn1 = fmaxf(m1, mx1), mn2 = fmaxf(m2, mx2);
        float cr1 = __expf(m1 - mn1), cr2 = __expf(m2 - mn2);
        float ls1 = 0.f, ls2 = 0.f;
        #pragma unroll
        for (int n0 = 0; n0 < 8; n0++) {
            float p0 = __expf(sacc[n0][0] - mn1);
            float p1 = __expf(sacc[n0][1] - mn1);
            float p2 = __expf(sacc[n0][2] - mn2);
            float p3 = __expf(sacc[n0][3] - mn2);
            ls1 += p0 + p1; ls2 += p2 + p3;
            sacc[n0][0] = p0; sacc[n0][1] = p1;
            sacc[n0][2] = p2; sacc[n0][3] = p3;
        }
        ls1 += __shfl_xor_sync(0xffffffffu, ls1, 1);
        ls1 += __shfl_xor_sync(0xffffffffu, ls1, 2);
        ls2 += __shfl_xor_sync(0xffffffffu, ls2, 1);
        ls2 += __shfl_xor_sync(0xffffffffu, ls2, 2);
        m1 = mn1; m2 = mn2;
        l1 = l1 * cr1 + ls1;
        l2 = l2 * cr2 + ls2;

        // ---- PV (3x bf16): P fragments built from sacc in registers ----
        #pragma unroll
        for (int n0 = 0; n0 < 8; n0++) {
            acc[n0][0] *= cr1; acc[n0][1] *= cr1;
            acc[n0][2] *= cr2; acc[n0][3] *= cr2;
        }
        #pragma unroll
        for (int kc = 0; kc < 4; kc++) {
            unsigned ah[4], al[4];
            split2(sacc[2*kc][0],   sacc[2*kc][1],   ah[0], al[0]);
            split2(sacc[2*kc][2],   sacc[2*kc][3],   ah[1], al[1]);
            split2(sacc[2*kc+1][0], sacc[2*kc+1][1], ah[2], al[2]);
            split2(sacc[2*kc+1][2], sacc[2*kc+1][3], ah[3], al[3]);
            #pragma unroll
            for (int n0p = 0; n0p < 4; n0p++) {
                unsigned bh[4], bl[4];
                int br = (n0p*16 + brow_off)*KW + kc*8 + bcol_q;
                ldsm_x4(bh, &Vh[br]);
                ldsm_x4(bl, &Vl[br]);
                mma16(acc[2*n0p],   ah, bh);
                mma16(acc[2*n0p],   ah, bl);
                mma16(acc[2*n0p],   al, bh);
                mma16(acc[2*n0p+1], ah, bh+2);
                mma16(acc[2*n0p+1], ah, bl+2);
                mma16(acc[2*n0p+1], al, bh+2);
            }
        }
    }

    float inv1 = 1.f / l1;
    float inv2 = 1.f / l2;
    int row1 = qt*QR + r0;
    float* Cb = g_C + (size_t)b * SS * EE + (size_t)h * DK;
    #pragma unroll
    for (int n0 = 0; n0 < 8; n0++) {
        int cc = n0*8 + 2*t4;
        *(float2*)&Cb[(size_t)row1 * EE + cc] =
            make_float2(acc[n0][0]*inv1, acc[n0][1]*inv1);
        *(float2*)&Cb[(size_t)(row1+8) * EE + cc] =
            make_float2(acc[n0][2]*inv2, acc[n0][3]*inv2);
    }
}

// ---------------------------------------------------------------------------
extern "C" void kernel_launch(void* const* d_in, const int* in_sizes, int n_in,
                              void* d_out, int out_size)
{
    const float* q    = (const float*)d_in[0];
    const float* k    = (const float*)d_in[1];
    const float* v    = (const float*)d_in[2];
    const int*   mask = (const int*)  d_in[3];
    const float* Wq   = (const float*)d_in[4];
    const float* Wk   = (const float*)d_in[5];
    const float* Wv   = (const float*)d_in[6];
    const float* W    = (const float*)d_in[7];
    float* out = (float*)d_out;

    // Fused QKV projection: one wide GEMM, 128x128 tiles
    gemm_kernel<<<dim3((BB*SS)/128, (3*EE)/128), 256>>>(q, k, v, Wq, Wk, Wv,
                                                        nullptr, nullptr, 0);

    // Flash attention (3xBF16, register-resident softmax, 2 CTAs/SM)
    flash_kernel<<<dim3(SS/QR, HH, BB), 256>>>(mask);

    // Output projection, 128x128 tiles
    gemm_kernel<<<dim3((BB*SS)/128, EE/128), 256>>>(nullptr, nullptr, nullptr,
                                                    nullptr, nullptr, nullptr, W, out, 1);
}

// round 13
// speedup vs baseline: 1.5871x; 1.0527x over previous
#include <cuda_runtime.h>
#include <cuda_bf16.h>
#include <math.h>

#define BB 2
#define SS 2048
#define EE 768
#define HH 12
#define DK 64

// Packed bf16x2 hi/lo interchange buffers (allocation-free)
__device__ unsigned g_Qh[BB*HH*SS*32], g_Ql[BB*HH*SS*32];  // [bhs][dk2], pre-scaled 1/8
__device__ unsigned g_Kh[BB*HH*SS*32], g_Kl[BB*HH*SS*32];  // [bhs][dk2]
__device__ unsigned g_Vh[BB*HH*SS*32], g_Vl[BB*HH*SS*32];  // [bhs][dk2]
__device__ unsigned g_Ch[BB*SS*384],  g_Cl[BB*SS*384];     // concat [m][e2]

// Split two floats into packed bf16x2 hi and lo words (lo = residual).
__device__ __forceinline__ void split2(float x0, float x1, unsigned& hi, unsigned& lo) {
    __nv_bfloat162 h2 = __floats2bfloat162_rn(x0, x1);
    float h0 = __bfloat162float(__low2bfloat16(h2));
    float h1 = __bfloat162float(__high2bfloat16(h2));
    __nv_bfloat162 l2 = __floats2bfloat162_rn(x0 - h0, x1 - h1);
    hi = *reinterpret_cast<unsigned*>(&h2);
    lo = *reinterpret_cast<unsigned*>(&l2);
}

// D += A*B, m16n8k16 bf16, A row-major, B col-major, f32 accumulate.
__device__ __forceinline__ void mma16(float c[4], const unsigned a[4], const unsigned* b) {
    asm volatile(
        "mma.sync.aligned.m16n8k16.row.col.f32.bf16.bf16.f32 "
        "{%0,%1,%2,%3},{%4,%5,%6,%7},{%8,%9},{%0,%1,%2,%3};"
        : "+f"(c[0]), "+f"(c[1]), "+f"(c[2]), "+f"(c[3])
        : "r"(a[0]), "r"(a[1]), "r"(a[2]), "r"(a[3]), "r"(b[0]), "r"(b[1]));
}

__device__ __forceinline__ void ldsm_x4(unsigned r[4], const void* p) {
    unsigned addr = (unsigned)__cvta_generic_to_shared(p);
    asm volatile("ldmatrix.sync.aligned.m8n8.x4.shared.b16 {%0,%1,%2,%3}, [%4];"
                 : "=r"(r[0]), "=r"(r[1]), "=r"(r[2]), "=r"(r[3]) : "r"(addr));
}

__device__ __forceinline__ void ldsm_x4_trans(unsigned r[4], const void* p) {
    unsigned addr = (unsigned)__cvta_generic_to_shared(p);
    asm volatile("ldmatrix.sync.aligned.m8n8.x4.trans.shared.b16 {%0,%1,%2,%3}, [%4];"
                 : "=r"(r[0]), "=r"(r[1]), "=r"(r[2]), "=r"(r[3]) : "r"(addr));
}

#define GW 20

// ---------------------------------------------------------------------------
// Fused QKV GEMM: X[4096,768] @ Wall[768,2304], 128x128 tiles, 256 threads,
// register-prefetch pipelined. grid=(32,18). Epilogue writes PACKED hi/lo
// bf16x2 Q (x 1/8), K, V.
// ---------------------------------------------------------------------------
__global__ __launch_bounds__(256) void qkv_gemm_kernel(
    const float* __restrict__ Xq, const float* __restrict__ Xk, const float* __restrict__ Xv,
    const float* __restrict__ Wq, const float* __restrict__ Wk, const float* __restrict__ Wv)
{
    __shared__ unsigned Ah[128*GW], Al[128*GW];   // [row][k2]
    __shared__ unsigned Bh[128*GW], Bl[128*GW];   // [n][k2]

    int bx = blockIdx.x, by = blockIdx.y;
    int t = threadIdx.x, w = t >> 5, l = t & 31;
    int t4 = l & 3;
    int g = l >> 2;
    int lj = l >> 3, lr = l & 7;
    int m0 = bx * 128;
    int n0 = by * 128;

    int which = n0 / EE;
    int rem = n0 - which * EE;               // multiple of 128
    const float* A  = (which == 0) ? Xq : (which == 1) ? Xk : Xv;
    const float* Ws = (which == 0) ? Wq : (which == 1) ? Wk : Wv;
    const float* Bbase = Ws + (size_t)(rem / 64) * EE * DK;

    float acc[16][4] = {};
    int r0 = 16*w + g;

    int arow = 16*w + lr + (lj & 1) * 8;
    int acol_q = (lj >> 1) * 4;
    int brow_off = lr + (lj >> 1) * 8;
    int bcol_q = (lj & 1) * 4;

    int ar = t >> 4, ak2 = t & 15;
    int bn = t & 127, bk2 = t >> 7;
    int hsel = bn >> 6;
    size_t bcol_off = (size_t)hsel * EE * DK + (bn & 63);

    float2 pa[8];
    float  pb0[8], pb1[8];

    #pragma unroll
    for (int i = 0; i < 8; i++)
        pa[i] = *(const float2*)&A[(size_t)(m0 + ar + i*16) * EE + 2*ak2];
    #pragma unroll
    for (int i = 0; i < 8; i++) {
        pb0[i] = Bbase[(size_t)(2*(bk2 + i*2))     * DK + bcol_off];
        pb1[i] = Bbase[(size_t)(2*(bk2 + i*2) + 1) * DK + bcol_off];
    }

    for (int k0 = 0; k0 < EE; k0 += 32) {
        __syncthreads();
        #pragma unroll
        for (int i = 0; i < 8; i++)
            split2(pa[i].x, pa[i].y, Ah[(ar + i*16)*GW + ak2], Al[(ar + i*16)*GW + ak2]);
        #pragma unroll
        for (int i = 0; i < 8; i++)
            split2(pb0[i], pb1[i], Bh[bn*GW + bk2 + i*2], Bl[bn*GW + bk2 + i*2]);
        __syncthreads();

        if (k0 + 32 < EE) {
            int kn = k0 + 32;
            #pragma unroll
            for (int i = 0; i < 8; i++)
                pa[i] = *(const float2*)&A[(size_t)(m0 + ar + i*16) * EE + kn + 2*ak2];
            #pragma unroll
            for (int i = 0; i < 8; i++) {
                pb0[i] = Bbase[(size_t)(kn + 2*(bk2 + i*2))     * DK + bcol_off];
                pb1[i] = Bbase[(size_t)(kn + 2*(bk2 + i*2) + 1) * DK + bcol_off];
            }
        }

        #pragma unroll
        for (int kc = 0; kc < 2; kc++) {
            unsigned ah[4], al[4];
            ldsm_x4(ah, &Ah[arow*GW + kc*8 + acol_q]);
            ldsm_x4(al, &Al[arow*GW + kc*8 + acol_q]);
            #pragma unroll
            for (int n0p = 0; n0p < 8; n0p++) {
                unsigned bh[4], bl[4];
                int br = (n0p*16 + brow_off)*GW + kc*8 + bcol_q;
                ldsm_x4(bh, &Bh[br]);
                ldsm_x4(bl, &Bl[br]);
                mma16(acc[2*n0p],   ah, bh);
                mma16(acc[2*n0p],   ah, bl);
                mma16(acc[2*n0p],   al, bh);
                mma16(acc[2*n0p+1], ah, bh+2);
                mma16(acc[2*n0p+1], ah, bl+2);
                mma16(acc[2*n0p+1], al, bh+2);
            }
        }
    }

    // Epilogue: pack hi/lo; Q gets the 1/8 softmax scale here.
    unsigned* Gh = (which == 0) ? g_Qh : (which == 1) ? g_Kh : g_Vh;
    unsigned* Gl = (which == 0) ? g_Ql : (which == 1) ? g_Kl : g_Vl;
    float sc = (which == 0) ? 0.125f : 1.0f;

    int rg1 = m0 + r0, rg2 = rg1 + 8;
    int b1 = rg1 >> 11, s1 = rg1 & 2047;
    int b2 = rg2 >> 11, s2 = rg2 & 2047;
    #pragma unroll
    for (int nb = 0; nb < 16; nb++) {
        int nloc = nb*8 + 2*t4;
        int head = (rem + nloc) >> 6;
        int wd = (nloc & 63) >> 1;
        size_t p1 = ((size_t)(b1*HH + head)*SS + s1) * 32 + wd;
        size_t p2 = ((size_t)(b2*HH + head)*SS + s2) * 32 + wd;
        unsigned hi, lo;
        split2(acc[nb][0]*sc, acc[nb][1]*sc, hi, lo);
        Gh[p1] = hi; Gl[p1] = lo;
        split2(acc[nb][2]*sc, acc[nb][3]*sc, hi, lo);
        Gh[p2] = hi; Gl[p2] = lo;
    }
}

// ---------------------------------------------------------------------------
// Flash attention, 3xBF16, register-resident softmax, ALL-COPY staging.
// grid=(S/128, H, B), block=256 (8 warps). K and V both stored [key][dk2];
// V B-fragments via ldmatrix.trans (packs pairs along keys). Epilogue writes
// packed C hi/lo.
// ---------------------------------------------------------------------------
#define KW 36
#define QR 128

__global__ __launch_bounds__(256, 2) void flash_kernel(const int* __restrict__ mask)
{
    __shared__ unsigned SB[4*64*KW];            // Kh | Kl | Vh | Vl
    unsigned* Kh = SB;
    unsigned* Kl = SB + 64*KW;
    unsigned* Vh = SB + 2*64*KW;                // [key][dk2] (same layout as K)
    unsigned* Vl = SB + 3*64*KW;

    int qt = blockIdx.x, h = blockIdx.y, b = blockIdx.z;
    int t = threadIdx.x, w = t >> 5, l = t & 31;
    int t4 = l & 3;
    int g = l >> 2;
    int lj = l >> 3, lr = l & 7;
    int r0 = 16*w + g;

    size_t qbase = ((size_t)(b*HH + h)*SS + qt*QR) * 32;
    size_t kvbase = (size_t)(b*HH + h) * SS * 32;
    const int* Mp = mask + ((size_t)b*SS + qt*QR) * SS;

    int arow = 16*w + lr + (lj & 1) * 8;
    int acol_q = (lj >> 1) * 4;
    int brow_off = lr + (lj >> 1) * 8;       // K (non-trans)
    int bcol_q = (lj & 1) * 4;
    int vrow_off = (lj & 1) * 8 + lr;        // V (trans): rows = keys
    int vcol_q = (lj >> 1) * 4;              // word col = dk/2 quadrant

    // Stage Q words (pre-scaled, packed), pull fragments to regs.
    #pragma unroll
    for (int i = 0; i < 16; i++) {
        int idx = t + i * 256;
        int r = idx >> 5, k2 = idx & 31;
        SB[r*KW + k2]         = g_Qh[qbase + r*32 + k2];
        SB[QR*KW + r*KW + k2] = g_Ql[qbase + r*32 + k2];
    }
    __syncthreads();

    unsigned qfh[4][4], qfl[4][4];
    #pragma unroll
    for (int kc = 0; kc < 4; kc++) {
        ldsm_x4(qfh[kc], &SB[arow*KW + kc*8 + acol_q]);
        ldsm_x4(qfl[kc], &SB[QR*KW + arow*KW + kc*8 + acol_q]);
    }

    float acc[8][4] = {};
    float m1 = -INFINITY, m2 = -INFINITY, l1 = 0.f, l2 = 0.f;

    int kr = t >> 5, kk2 = t & 31;          // staging: rows kr + i*8

    for (int kt = 0; kt < SS/64; kt++) {
        __syncthreads();
        size_t tb = kvbase + (size_t)(kt*64) * 32;
        #pragma unroll
        for (int i = 0; i < 8; i++) {
            size_t src = tb + (size_t)(kr + i*8)*32 + kk2;
            int dst = (kr + i*8)*KW + kk2;
            Kh[dst] = g_Kh[src];
            Kl[dst] = g_Kl[src];
            Vh[dst] = g_Vh[src];
            Vl[dst] = g_Vl[src];
        }
        __syncthreads();

        // ---- QK^T (3x bf16, ldmatrix B from K) ----
        float sacc[8][4] = {};
        #pragma unroll
        for (int kc = 0; kc < 4; kc++) {
            #pragma unroll
            for (int n0p = 0; n0p < 4; n0p++) {
                unsigned bh[4], bl[4];
                int br = (n0p*16 + brow_off)*KW + kc*8 + bcol_q;
                ldsm_x4(bh, &Kh[br]);
                ldsm_x4(bl, &Kl[br]);
                mma16(sacc[2*n0p],   qfh[kc], bh);
                mma16(sacc[2*n0p],   qfh[kc], bl);
                mma16(sacc[2*n0p],   qfl[kc], bh);
                mma16(sacc[2*n0p+1], qfh[kc], bh+2);
                mma16(sacc[2*n0p+1], qfh[kc], bl+2);
                mma16(sacc[2*n0p+1], qfl[kc], bh+2);
            }
        }

        // ---- mask + online softmax, all in registers ----
        const int* Mr1 = Mp + (size_t)r0 * SS + kt*64;
        const int* Mr2 = Mp + (size_t)(r0 + 8) * SS + kt*64;
        #pragma unroll
        for (int n0 = 0; n0 < 8; n0++) {
            int2 ma = *(const int2*)&Mr1[n0*8 + 2*t4];
            int2 mb = *(const int2*)&Mr2[n0*8 + 2*t4];
            sacc[n0][0] = ma.x ? sacc[n0][0] : -1e9f;
            sacc[n0][1] = ma.y ? sacc[n0][1] : -1e9f;
            sacc[n0][2] = mb.x ? sacc[n0][2] : -1e9f;
            sacc[n0][3] = mb.y ? sacc[n0][3] : -1e9f;
        }
        float mx1 = -INFINITY, mx2 = -INFINITY;
        #pragma unroll
        for (int n0 = 0; n0 < 8; n0++) {
            mx1 = fmaxf(mx1, fmaxf(sacc[n0][0], sacc[n0][1]));
            mx2 = fmaxf(mx2, fmaxf(sacc[n0][2], sacc[n0][3]));
        }
        mx1 = fmaxf(mx1, __shfl_xor_sync(0xffffffffu, mx1, 1));
        mx1 = fmaxf(mx1, __shfl_xor_sync(0xffffffffu, mx1, 2));
        mx2 = fmaxf(mx2, __shfl_xor_sync(0xffffffffu, mx2, 1));
        mx2 = fmaxf(mx2, __shfl_xor_sync(0xffffffffu, mx2, 2));
        float mn1 = fmaxf(m1, mx1), mn2 = fmaxf(m2, mx2);
        float cr1 = __expf(m1 - mn1), cr2 = __expf(m2 - mn2);
        float ls1 = 0.f, ls2 = 0.f;
        #pragma unroll
        for (int n0 = 0; n0 < 8; n0++) {
            float p0 = __expf(sacc[n0][0] - mn1);
            float p1 = __expf(sacc[n0][1] - mn1);
            float p2 = __expf(sacc[n0][2] - mn2);
            float p3 = __expf(sacc[n0][3] - mn2);
            ls1 += p0 + p1; ls2 += p2 + p3;
            sacc[n0][0] = p0; sacc[n0][1] = p1;
            sacc[n0][2] = p2; sacc[n0][3] = p3;
        }
        ls1 += __shfl_xor_sync(0xffffffffu, ls1, 1);
        ls1 += __shfl_xor_sync(0xffffffffu, ls1, 2);
        ls2 += __shfl_xor_sync(0xffffffffu, ls2, 1);
        ls2 += __shfl_xor_sync(0xffffffffu, ls2, 2);
        m1 = mn1; m2 = mn2;
        l1 = l1 * cr1 + ls1;
        l2 = l2 * cr2 + ls2;

        // ---- PV (3x bf16): P frags from sacc; V B-frags via ldmatrix.trans ----
        #pragma unroll
        for (int n0 = 0; n0 < 8; n0++) {
            acc[n0][0] *= cr1; acc[n0][1] *= cr1;
            acc[n0][2] *= cr2; acc[n0][3] *= cr2;
        }
        #pragma unroll
        for (int kc = 0; kc < 4; kc++) {
            unsigned ah[4], al[4];
            split2(sacc[2*kc][0],   sacc[2*kc][1],   ah[0], al[0]);
            split2(sacc[2*kc][2],   sacc[2*kc][3],   ah[1], al[1]);
            split2(sacc[2*kc+1][0], sacc[2*kc+1][1], ah[2], al[2]);
            split2(sacc[2*kc+1][2], sacc[2*kc+1][3], ah[3], al[3]);
            #pragma unroll
            for (int n0p = 0; n0p < 4; n0p++) {
                unsigned bh[4], bl[4];
                int vbr = (kc*16 + vrow_off)*KW + n0p*8 + vcol_q;
                ldsm_x4_trans(bh, &Vh[vbr]);
                ldsm_x4_trans(bl, &Vl[vbr]);
                mma16(acc[2*n0p],   ah, bh);
                mma16(acc[2*n0p],   ah, bl);
                mma16(acc[2*n0p],   al, bh);
                mma16(acc[2*n0p+1], ah, bh+2);
                mma16(acc[2*n0p+1], ah, bl+2);
                mma16(acc[2*n0p+1], al, bh+2);
            }
        }
    }

    float inv1 = 1.f / l1;
    float inv2 = 1.f / l2;
    size_t row1 = (size_t)b*SS + qt*QR + r0;
    #pragma unroll
    for (int n0 = 0; n0 < 8; n0++) {
        int wd = h*32 + n0*4 + t4;
        unsigned hi, lo;
        split2(acc[n0][0]*inv1, acc[n0][1]*inv1, hi, lo);
        g_Ch[row1*384 + wd] = hi; g_Cl[row1*384 + wd] = lo;
        split2(acc[n0][2]*inv2, acc[n0][3]*inv2, hi, lo);
        g_Ch[(row1+8)*384 + wd] = hi; g_Cl[(row1+8)*384 + wd] = lo;
    }
}

// ---------------------------------------------------------------------------
// Output projection: packed C [4096, 384 words] @ Wo[768,768] -> f32 out.
// 128x128 tiles, 256 threads, pipelined. grid=(32, 6).
// ---------------------------------------------------------------------------
__global__ __launch_bounds__(256) void out_gemm_kernel(
    const float* __restrict__ Wo, float* __restrict__ outp)
{
    __shared__ unsigned Ah[128*GW], Al[128*GW];
    __shared__ unsigned Bh[128*GW], Bl[128*GW];

    int bx = blockIdx.x, by = blockIdx.y;
    int t = threadIdx.x, w = t >> 5, l = t & 31;
    int t4 = l & 3;
    int g = l >> 2;
    int lj = l >> 3, lr = l & 7;
    int m0 = bx * 128;
    int n0 = by * 128;

    const float* Bbase = Wo + n0;

    float acc[16][4] = {};
    int r0 = 16*w + g;

    int arow = 16*w + lr + (lj & 1) * 8;
    int acol_q = (lj >> 1) * 4;
    int brow_off = lr + (lj >> 1) * 8;
    int bcol_q = (lj & 1) * 4;

    int ar = t >> 4, ak2 = t & 15;
    int bn = t & 127, bk2 = t >> 7;

    unsigned pah[8], pal[8];
    float    pb0[8], pb1[8];

    #pragma unroll
    for (int i = 0; i < 8; i++) {
        size_t src = (size_t)(m0 + ar + i*16) * 384 + ak2;
        pah[i] = g_Ch[src];
        pal[i] = g_Cl[src];
    }
    #pragma unroll
    for (int i = 0; i < 8; i++) {
        pb0[i] = Bbase[(size_t)(2*(bk2 + i*2))     * EE + bn];
        pb1[i] = Bbase[(size_t)(2*(bk2 + i*2) + 1) * EE + bn];
    }

    for (int kw = 0; kw < 384; kw += 16) {
        __syncthreads();
        #pragma unroll
        for (int i = 0; i < 8; i++) {
            Ah[(ar + i*16)*GW + ak2] = pah[i];
            Al[(ar + i*16)*GW + ak2] = pal[i];
        }
        #pragma unroll
        for (int i = 0; i < 8; i++)
            split2(pb0[i], pb1[i], Bh[bn*GW + bk2 + i*2], Bl[bn*GW + bk2 + i*2]);
        __syncthreads();

        if (kw + 16 < 384) {
            int knw = kw + 16;
            #pragma unroll
            for (int i = 0; i < 8; i++) {
                size_t src = (size_t)(m0 + ar + i*16) * 384 + knw + ak2;
                pah[i] = g_Ch[src];
                pal[i] = g_Cl[src];
            }
            #pragma unroll
            for (int i = 0; i < 8; i++) {
                pb0[i] = Bbase[(size_t)(2*(knw + bk2 + i*2))     * EE + bn];
                pb1[i] = Bbase[(size_t)(2*(knw + bk2 + i*2) + 1) * EE + bn];
            }
        }

        #pragma unroll
        for (int kc = 0; kc < 2; kc++) {
            unsigned ah[4], al[4];
            ldsm_x4(ah, &Ah[arow*GW + kc*8 + acol_q]);
            ldsm_x4(al, &Al[arow*GW + kc*8 + acol_q]);
            #pragma unroll
            for (int n0p = 0; n0p < 8; n0p++) {
                unsigned bh[4], bl[4];
                int br = (n0p*16 + brow_off)*GW + kc*8 + bcol_q;
                ldsm_x4(bh, &Bh[br]);
                ldsm_x4(bl, &Bl[br]);
                mma16(acc[2*n0p],   ah, bh);
                mma16(acc[2*n0p],   ah, bl);
                mma16(acc[2*n0p],   al, bh);
                mma16(acc[2*n0p+1], ah, bh+2);
                mma16(acc[2*n0p+1], ah, bl+2);
                mma16(acc[2*n0p+1], al, bh+2);
            }
        }
    }

    int rg1 = m0 + r0, rg2 = rg1 + 8;
    #pragma unroll
    for (int nb = 0; nb < 16; nb++) {
        int cn = n0 + nb*8 + 2*t4;
        *(float2*)&outp[(size_t)rg1 * EE + cn] = make_float2(acc[nb][0], acc[nb][1]);
        *(float2*)&outp[(size_t)rg2 * EE + cn] = make_float2(acc[nb][2], acc[nb][3]);
    }
}

// ---------------------------------------------------------------------------
extern "C" void kernel_launch(void* const* d_in, const int* in_sizes, int n_in,
                              void* d_out, int out_size)
{
    const float* q    = (const float*)d_in[0];
    const float* k    = (const float*)d_in[1];
    const float* v    = (const float*)d_in[2];
    const int*   mask = (const int*)  d_in[3];
    const float* Wq   = (const float*)d_in[4];
    const float* Wk   = (const float*)d_in[5];
    const float* Wv   = (const float*)d_in[6];
    const float* W    = (const float*)d_in[7];
    float* out = (float*)d_out;

    // Fused QKV projection -> packed hi/lo Q(scaled)/K/V
    qkv_gemm_kernel<<<dim3((BB*SS)/128, (3*EE)/128), 256>>>(q, k, v, Wq, Wk, Wv);

    // Flash attention (copy staging, trans-ldmatrix V) -> packed C
    flash_kernel<<<dim3(SS/QR, HH, BB), 256>>>(mask);

    // Output projection (packed A)
    out_gemm_kernel<<<dim3((BB*SS)/128, EE/128), 256>>>(W, out);
}